// round 5
// baseline (speedup 1.0000x reference)
#include <cuda_runtime.h>
#include <cstdint>
#include <math.h>

#define NTOK   8192
#define DMODEL 1024
#define DFFE   512
#define NEXP   16
#define DFFS   1024

// ---------------- scratch (device globals; no allocations) ----------------
__device__ int   d_cnt[NEXP];
__device__ int   d_lists[NEXP * NTOK];               // per-expert slot lists (slot = tok*2+k)
__device__ int   d_sexp[2 * NTOK];                   // slot -> expert id
__device__ float d_gw[2 * NTOK];                     // gate weight per slot
__device__ float d_g1[(size_t)2 * NTOK * DFFE];      // stage-1 W1 GEMM out (33.5MB)
__device__ float d_g3[(size_t)2 * NTOK * DFFE];      // stage-1 W3 GEMM out (33.5MB)
__device__ float d_h[(size_t)2 * NTOK * DFFE];       // routed hidden per slot
__device__ float d_hs[(size_t)NTOK * DFFS];          // shared hidden
__device__ float d_ypart[(size_t)2 * NTOK * DMODEL]; // routed partial out per slot

__device__ __forceinline__ float fsigmoid(float v) { return 1.f / (1.f + __expf(-v)); }
__device__ __forceinline__ uint32_t f2tf32(float f) {
    uint32_t u; asm("cvt.rna.tf32.f32 %0, %1;" : "=r"(u) : "f"(f)); return u;
}

__device__ __forceinline__ void mma_tf32(float* c, const uint32_t* a, uint32_t b0, uint32_t b1) {
    asm volatile("mma.sync.aligned.m16n8k8.row.col.f32.tf32.tf32.f32 "
        "{%0,%1,%2,%3}, {%4,%5,%6,%7}, {%8,%9}, {%0,%1,%2,%3};"
        : "+f"(c[0]), "+f"(c[1]), "+f"(c[2]), "+f"(c[3])
        : "r"(a[0]), "r"(a[1]), "r"(a[2]), "r"(a[3]), "r"(b0), "r"(b1));
}

// ---------------- smem layout ----------------
#define BK       16
#define PITCH    20
#define BUFBYTES (128 * PITCH * 4)      // 10240
#define ABUF_OFF 0                      // 2 buffers
#define BBUF_OFF (2 * BUFBYTES)
#define SLOT_OFF (4 * BUFBYTES)         // 40960: 128 ints
#define BIAS_OFF (SLOT_OFF + 512)       // 128 floats
#define SMEM_TOTAL (BIAS_OFF + 512)     // 41984

__device__ __forceinline__ void sts_tf32(char* buf, uint32_t off, float4 v) {
    *(uint4*)(buf + off) = make_uint4(f2tf32(v.x), f2tf32(v.y), f2tf32(v.z), f2tf32(v.w));
}

// ---------------- zero counters ----------------
__global__ void zero_cnt_kernel() {
    if (threadIdx.x < NEXP) d_cnt[threadIdx.x] = 0;
}

// ---------------- gate: one warp per token ----------------
__global__ void gate_kernel(const float* __restrict__ x,
                            const float* __restrict__ gw,
                            const float* __restrict__ ebias)
{
    int warp = (blockIdx.x * blockDim.x + threadIdx.x) >> 5;
    int lane = threadIdx.x & 31;
    if (warp >= NTOK) return;
    const float* xr = x + (size_t)warp * DMODEL;
    float xv[32];
#pragma unroll
    for (int j = 0; j < 32; j++) xv[j] = xr[lane + 32 * j];
    float logits[NEXP];
#pragma unroll
    for (int e = 0; e < NEXP; e++) {
        const float* wr = gw + e * DMODEL;
        float acc = 0.f;
#pragma unroll
        for (int j = 0; j < 32; j++) acc += xv[j] * wr[lane + 32 * j];
#pragma unroll
        for (int o = 16; o > 0; o >>= 1) acc += __shfl_xor_sync(0xffffffffu, acc, o);
        logits[e] = acc;
    }
    if (lane == 0) {
        int i0 = -1, i1 = -1;
        float v0 = -INFINITY, v1 = -INFINITY;
#pragma unroll
        for (int e = 0; e < NEXP; e++) {
            float b = logits[e] + ebias[e];
            if (b > v0) { v1 = v0; i1 = i0; v0 = b; i0 = e; }
            else if (b > v1) { v1 = b; i1 = e; }
        }
        float s0 = fsigmoid(logits[i0]);
        float s1 = fsigmoid(logits[i1]);
        float inv = 1.f / (s0 + s1 + 1e-10f);
        int p0 = atomicAdd(&d_cnt[i0], 1);
        d_lists[i0 * NTOK + p0] = warp * 2 + 0;
        d_gw[warp * 2 + 0] = s0 * inv;
        d_sexp[warp * 2 + 0] = i0;
        int p1 = atomicAdd(&d_cnt[i1], 1);
        d_lists[i1 * NTOK + p1] = warp * 2 + 1;
        d_gw[warp * 2 + 1] = s1 * inv;
        d_sexp[warp * 2 + 1] = i1;
    }
}

// ---------------- unified 128x128x16 tf32 GEMM ----------------
// GATHER: 0 = dense rows, 1 = gather token (slot>>1), 2 = gather slot
// EPI:    0 = store raw acc to Out[orow]
//         1 = (acc + bias) * d_gw[slot] -> Out[orow]   (routed stage 2)
//         2 = acc + bias + ypart[2m] + ypart[2m+1] -> Out[m]  (shared stage 2)
template<int GATHER, int EPI>
__global__ void __launch_bounds__(256, 2)
gemm128(const float* __restrict__ A, const float* __restrict__ Wb,
        const float* __restrict__ bb, float* __restrict__ Out,
        int K, int NW, int ldo)
{
    int e  = blockIdx.z;
    int m0 = blockIdx.y * 128;
    int n0 = blockIdx.x * 128;
    int Mv = NTOK;
    const int* list = d_lists + e * NTOK;
    if (GATHER != 0) { Mv = d_cnt[e]; if (m0 >= Mv) return; }
    const float* W = Wb + (size_t)e * NW * K;

    extern __shared__ char smem[];
    int*   sslot = (int*)(smem + SLOT_OFF);
    float* sBB   = (float*)(smem + BIAS_OFF);

    int tid = threadIdx.x;
    if (tid < 128) {
        int m = m0 + tid;
        sslot[tid] = (GATHER != 0) ? list[m < Mv ? m : Mv - 1] : m;
    } else if (EPI != 0) {
        sBB[tid - 128] = bb[(size_t)e * NW + n0 + (tid - 128)];
    }
    __syncthreads();

    // loader: 2 float4 per thread per matrix per 128x16 tile
    const float* aSrc[2]; const float* bSrc[2]; uint32_t dstOff[2];
#pragma unroll
    for (int i = 0; i < 2; i++) {
        int idx = tid + i * 256;            // 0..511
        int row = idx >> 2, kq = idx & 3;
        int slot = sslot[row];
        int ar = (GATHER == 1) ? (slot >> 1) : slot;
        aSrc[i] = A + (size_t)ar * K + kq * 4;
        bSrc[i] = W + (size_t)(n0 + row) * K + kq * 4;
        dstOff[i] = (uint32_t)(row * PITCH + kq * 4) * 4;
    }

    int wid = tid >> 5, lane = tid & 31;
    int wm = wid & 3, wn = wid >> 2;
    int lr = lane >> 2, lc = lane & 3;

    float acc[2][8][4] = {};

    int T = K / BK;
    float4 ra[2], rb[2];
#pragma unroll
    for (int i = 0; i < 2; i++) { ra[i] = *(const float4*)aSrc[i]; rb[i] = *(const float4*)bSrc[i]; }
    {
        char* aB = smem + ABUF_OFF;
        char* bB = smem + BBUF_OFF;
#pragma unroll
        for (int i = 0; i < 2; i++) { sts_tf32(aB, dstOff[i], ra[i]); sts_tf32(bB, dstOff[i], rb[i]); }
    }
    __syncthreads();

    for (int t = 0; t < T; t++) {
        // prefetch next tile from global
        if (t + 1 < T) {
            int k0 = (t + 1) * BK;
#pragma unroll
            for (int i = 0; i < 2; i++) {
                ra[i] = *(const float4*)(aSrc[i] + k0);
                rb[i] = *(const float4*)(bSrc[i] + k0);
            }
        }
        // compute from current buffer
        const uint32_t* Asm = (const uint32_t*)(smem + ABUF_OFF + (t & 1) * BUFBYTES);
        const uint32_t* Bsm = (const uint32_t*)(smem + BBUF_OFF + (t & 1) * BUFBYTES);
#pragma unroll
        for (int kk = 0; kk < 2; kk++) {
            int k0 = kk * 8;
            uint32_t a[2][4];
#pragma unroll
            for (int mf = 0; mf < 2; mf++) {
                int r = wm * 32 + mf * 16 + lr;
                a[mf][0] = Asm[r * PITCH + k0 + lc];
                a[mf][1] = Asm[(r + 8) * PITCH + k0 + lc];
                a[mf][2] = Asm[r * PITCH + k0 + 4 + lc];
                a[mf][3] = Asm[(r + 8) * PITCH + k0 + 4 + lc];
            }
#pragma unroll
            for (int f = 0; f < 8; f++) {
                int br = wn * 64 + 8 * f;
                uint32_t b0 = Bsm[(br + lr) * PITCH + k0 + lc];
                uint32_t b1 = Bsm[(br + lr) * PITCH + k0 + 4 + lc];
                mma_tf32(acc[0][f], a[0], b0, b1);
                mma_tf32(acc[1][f], a[1], b0, b1);
            }
        }
        // store next tile into the other buffer (safe: sync at end of prev iter
        // guarantees all reads of that buffer completed)
        if (t + 1 < T) {
            char* aB = smem + ABUF_OFF + ((t + 1) & 1) * BUFBYTES;
            char* bB = smem + BBUF_OFF + ((t + 1) & 1) * BUFBYTES;
#pragma unroll
            for (int i = 0; i < 2; i++) { sts_tf32(aB, dstOff[i], ra[i]); sts_tf32(bB, dstOff[i], rb[i]); }
        }
        __syncthreads();
    }

#pragma unroll
    for (int mf = 0; mf < 2; mf++) {
#pragma unroll
        for (int half = 0; half < 2; half++) {
            int rt = wm * 32 + mf * 16 + half * 8 + lr;
            int m = m0 + rt;
            if (GATHER != 0 && m >= Mv) continue;
            int orow = sslot[rt];
            float sc = (EPI == 1) ? d_gw[orow] : 0.f;
#pragma unroll
            for (int f = 0; f < 8; f++) {
                int nb = wn * 64 + 8 * f + 2 * lc;
                float c0 = acc[mf][f][half * 2 + 0];
                float c1 = acc[mf][f][half * 2 + 1];
                if (EPI == 0) {
                    *(float2*)(Out + (size_t)orow * ldo + n0 + nb) = make_float2(c0, c1);
                } else if (EPI == 1) {
                    c0 = (c0 + sBB[nb]) * sc;
                    c1 = (c1 + sBB[nb + 1]) * sc;
                    *(float2*)(Out + (size_t)orow * ldo + n0 + nb) = make_float2(c0, c1);
                } else {
                    const float* y0 = d_ypart + (size_t)(2 * m) * DMODEL + n0 + nb;
                    const float* y1 = y0 + DMODEL;
                    float2 a2 = *(const float2*)y0;
                    float2 b2 = *(const float2*)y1;
                    *(float2*)(Out + (size_t)m * ldo + n0 + nb) =
                        make_float2(c0 + sBB[nb] + a2.x + b2.x,
                                    c1 + sBB[nb + 1] + a2.y + b2.y);
                }
            }
        }
    }
}

// ---------------- elementwise SwiGLU ----------------
// H[row][0:N) = silu(g1 + b1[e]) * (g3 + b3[e]);  e = d_sexp[row] if USEEXP else 0
template<int USEEXP>
__global__ void swiglu_kernel(const float* __restrict__ g1, const float* __restrict__ g3,
                              const float* __restrict__ b1, const float* __restrict__ b3,
                              float* __restrict__ H, int N)
{
    size_t idx = ((size_t)blockIdx.x * blockDim.x + threadIdx.x) * 4;
    int row = (int)(idx / N);
    int col = (int)(idx % N);
    int e = USEEXP ? d_sexp[row] : 0;
    float4 v1 = *(const float4*)(g1 + idx);
    float4 v3 = *(const float4*)(g3 + idx);
    float4 bb1 = *(const float4*)(b1 + (size_t)e * N + col);
    float4 bb3 = *(const float4*)(b3 + (size_t)e * N + col);
    float g, u; float4 ov;
    g = v1.x + bb1.x; u = v3.x + bb3.x; ov.x = g * fsigmoid(g) * u;
    g = v1.y + bb1.y; u = v3.y + bb3.y; ov.y = g * fsigmoid(g) * u;
    g = v1.z + bb1.z; u = v3.z + bb3.z; ov.z = g * fsigmoid(g) * u;
    g = v1.w + bb1.w; u = v3.w + bb3.w; ov.w = g * fsigmoid(g) * u;
    *(float4*)(H + idx) = ov;
}

// ---------------- launch ----------------
extern "C" void kernel_launch(void* const* d_in, const int* in_sizes, int n_in,
                              void* d_out, int out_size)
{
    const float* x   = (const float*)d_in[0];
    const float* gw  = (const float*)d_in[1];
    const float* eb  = (const float*)d_in[2];
    const float* w1  = (const float*)d_in[3];
    const float* b1  = (const float*)d_in[4];
    const float* w3  = (const float*)d_in[5];
    const float* b3  = (const float*)d_in[6];
    const float* w2  = (const float*)d_in[7];
    const float* b2  = (const float*)d_in[8];
    const float* sw1 = (const float*)d_in[9];
    const float* sb1 = (const float*)d_in[10];
    const float* sw3 = (const float*)d_in[11];
    const float* sb3 = (const float*)d_in[12];
    const float* sw2 = (const float*)d_in[13];
    const float* sb2 = (const float*)d_in[14];
    float* out = (float*)d_out;

    float* g1_p; cudaGetSymbolAddress((void**)&g1_p, d_g1);
    float* g3_p; cudaGetSymbolAddress((void**)&g3_p, d_g3);
    float* h_p;  cudaGetSymbolAddress((void**)&h_p,  d_h);
    float* hs_p; cudaGetSymbolAddress((void**)&hs_p, d_hs);
    float* yp_p; cudaGetSymbolAddress((void**)&yp_p, d_ypart);

    cudaFuncSetAttribute(gemm128<1,0>, cudaFuncAttributeMaxDynamicSharedMemorySize, SMEM_TOTAL);
    cudaFuncSetAttribute(gemm128<2,1>, cudaFuncAttributeMaxDynamicSharedMemorySize, SMEM_TOTAL);
    cudaFuncSetAttribute(gemm128<0,0>, cudaFuncAttributeMaxDynamicSharedMemorySize, SMEM_TOTAL);
    cudaFuncSetAttribute(gemm128<0,2>, cudaFuncAttributeMaxDynamicSharedMemorySize, SMEM_TOTAL);

    zero_cnt_kernel<<<1, 32>>>();
    gate_kernel<<<(NTOK * 32) / 256, 256>>>(x, gw, eb);

    // routed stage 1: two plain GEMMs (gather token rows), N=512, K=1024
    gemm128<1,0><<<dim3(DFFE / 128, NTOK / 128, NEXP), 256, SMEM_TOTAL>>>(
        x, w1, nullptr, g1_p, DMODEL, DFFE, DFFE);
    gemm128<1,0><<<dim3(DFFE / 128, NTOK / 128, NEXP), 256, SMEM_TOTAL>>>(
        x, w3, nullptr, g3_p, DMODEL, DFFE, DFFE);
    // SwiGLU over all 16384 slots x 512
    swiglu_kernel<1><<<(2 * NTOK * DFFE / 4) / 256, 256>>>(g1_p, g3_p, b1, b3, h_p, DFFE);

    // routed stage 2: gather slot rows, N=1024, K=512 -> ypart[slot]
    gemm128<2,1><<<dim3(DMODEL / 128, NTOK / 128, NEXP), 256, SMEM_TOTAL>>>(
        h_p, w2, b2, yp_p, DFFE, DMODEL, DMODEL);

    // shared stage 1: two dense GEMMs, N=1024, K=1024
    gemm128<0,0><<<dim3(DFFS / 128, NTOK / 128, 1), 256, SMEM_TOTAL>>>(
        x, sw1, nullptr, g1_p, DMODEL, DFFS, DFFS);
    gemm128<0,0><<<dim3(DFFS / 128, NTOK / 128, 1), 256, SMEM_TOTAL>>>(
        x, sw3, nullptr, g3_p, DMODEL, DFFS, DFFS);
    swiglu_kernel<0><<<(NTOK * DFFS / 4) / 256, 256>>>(g1_p, g3_p, sb1, sb3, hs_p, DFFS);

    // shared stage 2 + combine: dense, N=1024, K=1024 -> out
    gemm128<0,2><<<dim3(DMODEL / 128, NTOK / 128, 1), 256, SMEM_TOTAL>>>(
        hs_p, sw2, sb2, out, DMODEL, DMODEL, DMODEL);
}

// round 6
// speedup vs baseline: 1.0645x; 1.0645x over previous
#include <cuda_runtime.h>
#include <cstdint>
#include <math.h>

#define NTOK   8192
#define DMODEL 1024
#define DFFE   512
#define NEXP   16
#define DFFS   1024

// ---------------- scratch (device globals; no allocations) ----------------
__device__ int   d_cnt[NEXP];
__device__ int   d_lists[NEXP * NTOK];               // per-expert slot lists (slot = tok*2+k)
__device__ float d_gw[2 * NTOK];                     // gate weight per slot
__device__ float d_g1[(size_t)2 * NTOK * DFFS];      // stage-1 W1 GEMM out (biased)
__device__ float d_h[(size_t)2 * NTOK * DFFE];       // routed hidden per slot
__device__ float d_hs[(size_t)NTOK * DFFS];          // shared hidden
__device__ float d_ypart[(size_t)2 * NTOK * DMODEL]; // routed partial out per slot

__device__ __forceinline__ float fsigmoid(float v) { return 1.f / (1.f + __expf(-v)); }
__device__ __forceinline__ uint32_t f2tf32(float f) {
    uint32_t u; asm("cvt.rna.tf32.f32 %0, %1;" : "=r"(u) : "f"(f)); return u;
}
__device__ __forceinline__ uint32_t smem_u32(const void* p) {
    uint32_t a;
    asm("{ .reg .u64 t; cvta.to.shared.u64 t, %1; cvt.u32.u64 %0, t; }" : "=r"(a) : "l"(p));
    return a;
}

__device__ __forceinline__ void mma_tf32(float* c, const uint32_t* a, uint32_t b0, uint32_t b1) {
    asm volatile("mma.sync.aligned.m16n8k8.row.col.f32.tf32.tf32.f32 "
        "{%0,%1,%2,%3}, {%4,%5,%6,%7}, {%8,%9}, {%0,%1,%2,%3};"
        : "+f"(c[0]), "+f"(c[1]), "+f"(c[2]), "+f"(c[3])
        : "r"(a[0]), "r"(a[1]), "r"(a[2]), "r"(a[3]), "r"(b0), "r"(b1));
}
__device__ __forceinline__ void ldsm4(uint32_t* r, uint32_t addr) {
    asm volatile("ldmatrix.sync.aligned.m8n8.x4.shared.b16 {%0,%1,%2,%3}, [%4];"
        : "=r"(r[0]), "=r"(r[1]), "=r"(r[2]), "=r"(r[3]) : "r"(addr));
}

// ---------------- smem layout ----------------
// PITCH=20 floats: row stride 80B; 8 LDSM rows hit byte offsets
// {0,80,32,112,64,16,96,48} mod 128 -> 8 distinct bank groups: conflict-free.
#define BK       16
#define PITCH    20
#define BUFBYTES (128 * PITCH * 4)      // 10240
#define ABUF_OFF 0                      // 2 buffers
#define BBUF_OFF (2 * BUFBYTES)
#define SLOT_OFF (4 * BUFBYTES)         // 40960: 128 ints
#define BIAS_OFF (SLOT_OFF + 512)       // 128 floats
#define SMEM_TOTAL (BIAS_OFF + 512)     // 41984

__device__ __forceinline__ void sts_tf32(char* buf, uint32_t off, float4 v) {
    *(uint4*)(buf + off) = make_uint4(f2tf32(v.x), f2tf32(v.y), f2tf32(v.z), f2tf32(v.w));
}

// ---------------- zero counters ----------------
__global__ void zero_cnt_kernel() {
    if (threadIdx.x < NEXP) d_cnt[threadIdx.x] = 0;
}

// ---------------- gate: one warp per token ----------------
__global__ void gate_kernel(const float* __restrict__ x,
                            const float* __restrict__ gw,
                            const float* __restrict__ ebias)
{
    int warp = (blockIdx.x * blockDim.x + threadIdx.x) >> 5;
    int lane = threadIdx.x & 31;
    if (warp >= NTOK) return;
    const float* xr = x + (size_t)warp * DMODEL;
    float xv[32];
#pragma unroll
    for (int j = 0; j < 32; j++) xv[j] = xr[lane + 32 * j];
    float logits[NEXP];
#pragma unroll
    for (int e = 0; e < NEXP; e++) {
        const float* wr = gw + e * DMODEL;
        float acc = 0.f;
#pragma unroll
        for (int j = 0; j < 32; j++) acc += xv[j] * wr[lane + 32 * j];
#pragma unroll
        for (int o = 16; o > 0; o >>= 1) acc += __shfl_xor_sync(0xffffffffu, acc, o);
        logits[e] = acc;
    }
    if (lane == 0) {
        int i0 = -1, i1 = -1;
        float v0 = -INFINITY, v1 = -INFINITY;
#pragma unroll
        for (int e = 0; e < NEXP; e++) {
            float b = logits[e] + ebias[e];
            if (b > v0) { v1 = v0; i1 = i0; v0 = b; i0 = e; }
            else if (b > v1) { v1 = b; i1 = e; }
        }
        float s0 = fsigmoid(logits[i0]);
        float s1 = fsigmoid(logits[i1]);
        float inv = 1.f / (s0 + s1 + 1e-10f);
        int p0 = atomicAdd(&d_cnt[i0], 1);
        d_lists[i0 * NTOK + p0] = warp * 2 + 0;
        d_gw[warp * 2 + 0] = s0 * inv;
        int p1 = atomicAdd(&d_cnt[i1], 1);
        d_lists[i1 * NTOK + p1] = warp * 2 + 1;
        d_gw[warp * 2 + 1] = s1 * inv;
    }
}

// ---------------- unified 128x128x16 tf32 GEMM (ldmatrix fragments) ----------------
// GATHER: 0 = dense rows, 1 = gather token (slot>>1), 2 = gather slot
// EPI: 1 = (acc+bias)*d_gw[slot] -> Out[orow]          (routed stage 2)
//      2 = acc+bias+ypart[2m]+ypart[2m+1] -> Out[m]    (shared stage 2 + combine)
//      3 = acc+bias -> Out[orow]                       (W1 stage: biased g1)
//      4 = g=Aux[orow]; u=acc+bias; silu(g)*u -> Out   (W3 stage: fused SwiGLU)
template<int GATHER, int EPI>
__global__ void __launch_bounds__(256, 2)
gemm128(const float* __restrict__ A, const float* __restrict__ Wb,
        const float* __restrict__ bb, float* __restrict__ Out,
        const float* __restrict__ Aux, int K, int NW, int ldo)
{
    int e  = blockIdx.z;
    int m0 = blockIdx.y * 128;
    int n0 = blockIdx.x * 128;
    int Mv = NTOK;
    const int* list = d_lists + e * NTOK;
    if (GATHER != 0) { Mv = d_cnt[e]; if (m0 >= Mv) return; }
    const float* W = Wb + (size_t)e * NW * K;

    extern __shared__ char smem[];
    uint32_t sbase = smem_u32(smem);
    int*   sslot = (int*)(smem + SLOT_OFF);
    float* sBB   = (float*)(smem + BIAS_OFF);

    int tid = threadIdx.x;
    if (tid < 128) {
        int m = m0 + tid;
        sslot[tid] = (GATHER != 0) ? list[m < Mv ? m : Mv - 1] : m;
    } else {
        sBB[tid - 128] = bb[(size_t)e * NW + n0 + (tid - 128)];
    }
    __syncthreads();

    // global->smem writer: 2 float4 per thread per matrix per 128x16 tile
    const float* aSrc[2]; const float* bSrc[2]; uint32_t dstOff[2];
#pragma unroll
    for (int i = 0; i < 2; i++) {
        int idx = tid + i * 256;            // 0..511
        int row = idx >> 2, kq = idx & 3;
        int slot = sslot[row];
        int ar = (GATHER == 1) ? (slot >> 1) : slot;
        aSrc[i] = A + (size_t)ar * K + kq * 4;
        bSrc[i] = W + (size_t)(n0 + row) * K + kq * 4;
        dstOff[i] = (uint32_t)(row * PITCH + kq * 4) * 4;
    }

    int wid = tid >> 5, lane = tid & 31;
    int wm = wid & 3, wn = wid >> 2;
    int lr = lane >> 2, lc = lane & 3;
    int sel = lane >> 3, rr = lane & 7;

    // ldmatrix per-thread row addresses (byte offsets within buffer)
    uint32_t aOff[2], bOff[4];
#pragma unroll
    for (int mf = 0; mf < 2; mf++)
        aOff[mf] = (uint32_t)(((wm * 32 + mf * 16 + (sel & 1) * 8 + rr) * PITCH + (sel >> 1) * 4) * 4);
#pragma unroll
    for (int fp = 0; fp < 4; fp++)
        bOff[fp] = (uint32_t)(((wn * 64 + fp * 16 + (sel >> 1) * 8 + rr) * PITCH + (sel & 1) * 4) * 4);

    float acc[2][8][4] = {};

    int T = K / BK;
    float4 ra[2], rb[2];
#pragma unroll
    for (int i = 0; i < 2; i++) { ra[i] = *(const float4*)aSrc[i]; rb[i] = *(const float4*)bSrc[i]; }
    {
        char* aB = smem + ABUF_OFF;
        char* bB = smem + BBUF_OFF;
#pragma unroll
        for (int i = 0; i < 2; i++) { sts_tf32(aB, dstOff[i], ra[i]); sts_tf32(bB, dstOff[i], rb[i]); }
    }
    __syncthreads();

    for (int t = 0; t < T; t++) {
        if (t + 1 < T) {
            int k0 = (t + 1) * BK;
#pragma unroll
            for (int i = 0; i < 2; i++) {
                ra[i] = *(const float4*)(aSrc[i] + k0);
                rb[i] = *(const float4*)(bSrc[i] + k0);
            }
        }
        uint32_t abuf = sbase + ABUF_OFF + (t & 1) * BUFBYTES;
        uint32_t bbuf = sbase + BBUF_OFF + (t & 1) * BUFBYTES;
#pragma unroll
        for (int kk = 0; kk < 2; kk++) {
            uint32_t koff = kk * 32;
            uint32_t a[2][4];
            ldsm4(a[0], abuf + aOff[0] + koff);
            ldsm4(a[1], abuf + aOff[1] + koff);
#pragma unroll
            for (int fp = 0; fp < 4; fp++) {
                uint32_t b[4];
                ldsm4(b, bbuf + bOff[fp] + koff);
                mma_tf32(acc[0][2 * fp],     a[0], b[0], b[1]);
                mma_tf32(acc[1][2 * fp],     a[1], b[0], b[1]);
                mma_tf32(acc[0][2 * fp + 1], a[0], b[2], b[3]);
                mma_tf32(acc[1][2 * fp + 1], a[1], b[2], b[3]);
            }
        }
        if (t + 1 < T) {
            char* aB = smem + ABUF_OFF + ((t + 1) & 1) * BUFBYTES;
            char* bB = smem + BBUF_OFF + ((t + 1) & 1) * BUFBYTES;
#pragma unroll
            for (int i = 0; i < 2; i++) { sts_tf32(aB, dstOff[i], ra[i]); sts_tf32(bB, dstOff[i], rb[i]); }
        }
        __syncthreads();
    }

#pragma unroll
    for (int mf = 0; mf < 2; mf++) {
#pragma unroll
        for (int half = 0; half < 2; half++) {
            int rt = wm * 32 + mf * 16 + half * 8 + lr;
            int m = m0 + rt;
            if (GATHER != 0 && m >= Mv) continue;
            int orow = sslot[rt];
            float sc = (EPI == 1) ? d_gw[orow] : 0.f;
#pragma unroll
            for (int f = 0; f < 8; f++) {
                int nb = wn * 64 + 8 * f + 2 * lc;
                float c0 = acc[mf][f][half * 2 + 0] + sBB[nb];
                float c1 = acc[mf][f][half * 2 + 1] + sBB[nb + 1];
                if (EPI == 1) {
                    *(float2*)(Out + (size_t)orow * ldo + n0 + nb) =
                        make_float2(c0 * sc, c1 * sc);
                } else if (EPI == 2) {
                    const float* y0 = d_ypart + (size_t)(2 * m) * DMODEL + n0 + nb;
                    const float* y1 = y0 + DMODEL;
                    float2 a2 = *(const float2*)y0;
                    float2 b2 = *(const float2*)y1;
                    *(float2*)(Out + (size_t)m * ldo + n0 + nb) =
                        make_float2(c0 + a2.x + b2.x, c1 + a2.y + b2.y);
                } else if (EPI == 3) {
                    *(float2*)(Out + (size_t)orow * ldo + n0 + nb) = make_float2(c0, c1);
                } else { // EPI == 4: fused SwiGLU (g from Aux, u = acc+bias)
                    float2 g2 = *(const float2*)(Aux + (size_t)orow * ldo + n0 + nb);
                    float h0 = g2.x * fsigmoid(g2.x) * c0;
                    float h1 = g2.y * fsigmoid(g2.y) * c1;
                    *(float2*)(Out + (size_t)orow * ldo + n0 + nb) = make_float2(h0, h1);
                }
            }
        }
    }
}

// ---------------- launch ----------------
extern "C" void kernel_launch(void* const* d_in, const int* in_sizes, int n_in,
                              void* d_out, int out_size)
{
    const float* x   = (const float*)d_in[0];
    const float* gw  = (const float*)d_in[1];
    const float* eb  = (const float*)d_in[2];
    const float* w1  = (const float*)d_in[3];
    const float* b1  = (const float*)d_in[4];
    const float* w3  = (const float*)d_in[5];
    const float* b3  = (const float*)d_in[6];
    const float* w2  = (const float*)d_in[7];
    const float* b2  = (const float*)d_in[8];
    const float* sw1 = (const float*)d_in[9];
    const float* sb1 = (const float*)d_in[10];
    const float* sw3 = (const float*)d_in[11];
    const float* sb3 = (const float*)d_in[12];
    const float* sw2 = (const float*)d_in[13];
    const float* sb2 = (const float*)d_in[14];
    float* out = (float*)d_out;

    float* g1_p; cudaGetSymbolAddress((void**)&g1_p, d_g1);
    float* h_p;  cudaGetSymbolAddress((void**)&h_p,  d_h);
    float* hs_p; cudaGetSymbolAddress((void**)&hs_p, d_hs);
    float* yp_p; cudaGetSymbolAddress((void**)&yp_p, d_ypart);

    cudaFuncSetAttribute(gemm128<1,3>, cudaFuncAttributeMaxDynamicSharedMemorySize, SMEM_TOTAL);
    cudaFuncSetAttribute(gemm128<1,4>, cudaFuncAttributeMaxDynamicSharedMemorySize, SMEM_TOTAL);
    cudaFuncSetAttribute(gemm128<2,1>, cudaFuncAttributeMaxDynamicSharedMemorySize, SMEM_TOTAL);
    cudaFuncSetAttribute(gemm128<0,3>, cudaFuncAttributeMaxDynamicSharedMemorySize, SMEM_TOTAL);
    cudaFuncSetAttribute(gemm128<0,4>, cudaFuncAttributeMaxDynamicSharedMemorySize, SMEM_TOTAL);
    cudaFuncSetAttribute(gemm128<0,2>, cudaFuncAttributeMaxDynamicSharedMemorySize, SMEM_TOTAL);

    zero_cnt_kernel<<<1, 32>>>();
    gate_kernel<<<(NTOK * 32) / 256, 256>>>(x, gw, eb);

    // routed stage 1a: g1 = x@W1^T + b1 (gather token rows), N=512, K=1024
    gemm128<1,3><<<dim3(DFFE / 128, NTOK / 128, NEXP), 256, SMEM_TOTAL>>>(
        x, w1, b1, g1_p, nullptr, DMODEL, DFFE, DFFE);
    // routed stage 1b: h = silu(g1) * (x@W3^T + b3)  (fused SwiGLU)
    gemm128<1,4><<<dim3(DFFE / 128, NTOK / 128, NEXP), 256, SMEM_TOTAL>>>(
        x, w3, b3, h_p, g1_p, DMODEL, DFFE, DFFE);
    // routed stage 2: ypart[slot] = (h@W2^T + b2) * gate_w, N=1024, K=512
    gemm128<2,1><<<dim3(DMODEL / 128, NTOK / 128, NEXP), 256, SMEM_TOTAL>>>(
        h_p, w2, b2, yp_p, nullptr, DFFE, DMODEL, DMODEL);

    // shared stage 1a/1b: dense, N=1024, K=1024
    gemm128<0,3><<<dim3(DFFS / 128, NTOK / 128, 1), 256, SMEM_TOTAL>>>(
        x, sw1, sb1, g1_p, nullptr, DMODEL, DFFS, DFFS);
    gemm128<0,4><<<dim3(DFFS / 128, NTOK / 128, 1), 256, SMEM_TOTAL>>>(
        x, sw3, sb3, hs_p, g1_p, DMODEL, DFFS, DFFS);

    // shared stage 2 + combine: out = hs@sW2^T + sb2 + ypart[2m] + ypart[2m+1]
    gemm128<0,2><<<dim3(DMODEL / 128, NTOK / 128, 1), 256, SMEM_TOTAL>>>(
        hs_p, sw2, sb2, out, nullptr, DMODEL, DMODEL, DMODEL);
}

// round 7
// speedup vs baseline: 1.2007x; 1.1279x over previous
#include <cuda_runtime.h>
#include <cuda_fp16.h>
#include <cstdint>
#include <math.h>

#define NTOK   8192
#define DMODEL 1024
#define DFFE   512
#define NEXP   16
#define DFFS   1024

// ---------------- scratch (device globals; no allocations) ----------------
__device__ int   d_cnt[NEXP];
__device__ int   d_lists[NEXP * NTOK];               // per-expert slot lists (slot = tok*2+k)
__device__ float d_gw[2 * NTOK];                     // gate weight per slot
__device__ float d_g1[(size_t)2 * NTOK * DFFS];      // stage-1 W1 GEMM out (biased)
__device__ float d_h[(size_t)2 * NTOK * DFFE];       // routed hidden per slot
__device__ float d_hs[(size_t)NTOK * DFFS];          // shared hidden
__device__ float d_ypart[(size_t)2 * NTOK * DMODEL]; // routed partial out per slot

__device__ __forceinline__ float fsigmoid(float v) { return 1.f / (1.f + __expf(-v)); }
__device__ __forceinline__ uint32_t smem_u32(const void* p) {
    uint32_t a;
    asm("{ .reg .u64 t; cvta.to.shared.u64 t, %1; cvt.u32.u64 %0, t; }" : "=r"(a) : "l"(p));
    return a;
}

// fp16 mma, fp32 accumulate: m16n8k16
__device__ __forceinline__ void mma_f16(float* c, const uint32_t* a, uint32_t b0, uint32_t b1) {
    asm volatile("mma.sync.aligned.m16n8k16.row.col.f32.f16.f16.f32 "
        "{%0,%1,%2,%3}, {%4,%5,%6,%7}, {%8,%9}, {%0,%1,%2,%3};"
        : "+f"(c[0]), "+f"(c[1]), "+f"(c[2]), "+f"(c[3])
        : "r"(a[0]), "r"(a[1]), "r"(a[2]), "r"(a[3]), "r"(b0), "r"(b1));
}
__device__ __forceinline__ void ldsm4(uint32_t* r, uint32_t addr) {
    asm volatile("ldmatrix.sync.aligned.m8n8.x4.shared.b16 {%0,%1,%2,%3}, [%4];"
        : "=r"(r[0]), "=r"(r[1]), "=r"(r[2]), "=r"(r[3]) : "r"(addr));
}
// pack 8 f32 -> 8 f16 (16B)
__device__ __forceinline__ uint4 pack_h8(float4 u, float4 v) {
    uint4 o;
    half2 h0 = __floats2half2_rn(u.x, u.y);
    half2 h1 = __floats2half2_rn(u.z, u.w);
    half2 h2 = __floats2half2_rn(v.x, v.y);
    half2 h3 = __floats2half2_rn(v.z, v.w);
    o.x = *(uint32_t*)&h0; o.y = *(uint32_t*)&h1;
    o.z = *(uint32_t*)&h2; o.w = *(uint32_t*)&h3;
    return o;
}

// ---------------- smem layout ----------------
// fp16 tile 128 rows x 16 k; row stride 48B (16 data halfs + 8 pad).
// LDSM 8-row addresses: 48*{0..7} mod 128 = {0,48,96,16,64,112,32,80} -> conflict-free.
#define BK       16
#define RS       48
#define BUFBYTES (128 * RS)             // 6144
#define ABUF_OFF 0                      // 2 buffers
#define BBUF_OFF (2 * BUFBYTES)
#define SLOT_OFF (4 * BUFBYTES)         // 24576: 128 ints
#define BIAS_OFF (SLOT_OFF + 512)       // 128 floats
#define SMEM_TOTAL (BIAS_OFF + 512)     // 25600

// ---------------- zero counters ----------------
__global__ void zero_cnt_kernel() {
    if (threadIdx.x < NEXP) d_cnt[threadIdx.x] = 0;
}

// ---------------- gate: one warp per token ----------------
__global__ void gate_kernel(const float* __restrict__ x,
                            const float* __restrict__ gw,
                            const float* __restrict__ ebias)
{
    int warp = (blockIdx.x * blockDim.x + threadIdx.x) >> 5;
    int lane = threadIdx.x & 31;
    if (warp >= NTOK) return;
    const float* xr = x + (size_t)warp * DMODEL;
    float xv[32];
#pragma unroll
    for (int j = 0; j < 32; j++) xv[j] = xr[lane + 32 * j];
    float logits[NEXP];
#pragma unroll
    for (int e = 0; e < NEXP; e++) {
        const float* wr = gw + e * DMODEL;
        float acc = 0.f;
#pragma unroll
        for (int j = 0; j < 32; j++) acc += xv[j] * wr[lane + 32 * j];
#pragma unroll
        for (int o = 16; o > 0; o >>= 1) acc += __shfl_xor_sync(0xffffffffu, acc, o);
        logits[e] = acc;
    }
    if (lane == 0) {
        int i0 = -1, i1 = -1;
        float v0 = -INFINITY, v1 = -INFINITY;
#pragma unroll
        for (int e = 0; e < NEXP; e++) {
            float b = logits[e] + ebias[e];
            if (b > v0) { v1 = v0; i1 = i0; v0 = b; i0 = e; }
            else if (b > v1) { v1 = b; i1 = e; }
        }
        float s0 = fsigmoid(logits[i0]);
        float s1 = fsigmoid(logits[i1]);
        float inv = 1.f / (s0 + s1 + 1e-10f);
        int p0 = atomicAdd(&d_cnt[i0], 1);
        d_lists[i0 * NTOK + p0] = warp * 2 + 0;
        d_gw[warp * 2 + 0] = s0 * inv;
        int p1 = atomicAdd(&d_cnt[i1], 1);
        d_lists[i1 * NTOK + p1] = warp * 2 + 1;
        d_gw[warp * 2 + 1] = s1 * inv;
    }
}

// ---------------- unified 128x128x16 fp16-mma GEMM ----------------
// GATHER: 0 = dense rows, 1 = gather token (slot>>1), 2 = gather slot
// EPI: 1 = (acc+bias)*d_gw[slot] -> Out[orow]          (routed stage 2)
//      2 = acc+bias+ypart[2m]+ypart[2m+1] -> Out[m]    (shared stage 2 + combine)
//      3 = acc+bias -> Out[orow]                       (W1 stage: biased g1)
//      4 = g=Aux[orow]; u=acc+bias; silu(g)*u -> Out   (W3 stage: fused SwiGLU)
template<int GATHER, int EPI>
__global__ void __launch_bounds__(256, 2)
gemm128(const float* __restrict__ A, const float* __restrict__ Wb,
        const float* __restrict__ bb, float* __restrict__ Out,
        const float* __restrict__ Aux, int K, int NW, int ldo)
{
    int e  = blockIdx.z;
    int m0 = blockIdx.y * 128;
    int n0 = blockIdx.x * 128;
    int Mv = NTOK;
    const int* list = d_lists + e * NTOK;
    if (GATHER != 0) { Mv = d_cnt[e]; if (m0 >= Mv) return; }
    const float* W = Wb + (size_t)e * NW * K;

    extern __shared__ char smem[];
    uint32_t sbase = smem_u32(smem);
    int*   sslot = (int*)(smem + SLOT_OFF);
    float* sBB   = (float*)(smem + BIAS_OFF);

    int tid = threadIdx.x;
    if (tid < 128) {
        int m = m0 + tid;
        sslot[tid] = (GATHER != 0) ? list[m < Mv ? m : Mv - 1] : m;
    } else {
        sBB[tid - 128] = bb[(size_t)e * NW + n0 + (tid - 128)];
    }
    __syncthreads();

    // writer: thread owns (row = tid>>1, halfk = tid&1): 8 fp32 -> 8 fp16 (16B)
    int wrow = tid >> 1, whalf = tid & 1;
    {
        // nothing
    }
    int aslot = sslot[wrow];
    int ar = (GATHER == 1) ? (aslot >> 1) : aslot;
    const float* aSrc = A + (size_t)ar * K + whalf * 8;
    const float* bSrc = W + (size_t)(n0 + wrow) * K + whalf * 8;
    uint32_t wOff = (uint32_t)(wrow * RS + whalf * 16);

    int wid = tid >> 5, lane = tid & 31;
    int wm = wid & 3, wn = wid >> 2;
    int lr = lane >> 2, lc = lane & 3;
    int mat = lane >> 3, rr = lane & 7;

    // ldmatrix addresses
    uint32_t aOff[2], bOff[4];
#pragma unroll
    for (int mf = 0; mf < 2; mf++)
        aOff[mf] = (uint32_t)((wm * 32 + mf * 16 + (mat & 1) * 8 + rr) * RS + (mat >> 1) * 16);
#pragma unroll
    for (int fp = 0; fp < 4; fp++)
        bOff[fp] = (uint32_t)((wn * 64 + fp * 16 + (mat >> 1) * 8 + rr) * RS + (mat & 1) * 16);

    float acc[2][8][4] = {};

    int T = K / BK;
    float4 ra0 = *(const float4*)aSrc,       ra1 = *(const float4*)(aSrc + 4);
    float4 rb0 = *(const float4*)bSrc,       rb1 = *(const float4*)(bSrc + 4);
    *(uint4*)(smem + ABUF_OFF + wOff) = pack_h8(ra0, ra1);
    *(uint4*)(smem + BBUF_OFF + wOff) = pack_h8(rb0, rb1);
    __syncthreads();

    for (int t = 0; t < T; t++) {
        if (t + 1 < T) {
            int k0 = (t + 1) * BK;
            ra0 = *(const float4*)(aSrc + k0); ra1 = *(const float4*)(aSrc + k0 + 4);
            rb0 = *(const float4*)(bSrc + k0); rb1 = *(const float4*)(bSrc + k0 + 4);
        }
        uint32_t abuf = sbase + ABUF_OFF + (t & 1) * BUFBYTES;
        uint32_t bbuf = sbase + BBUF_OFF + (t & 1) * BUFBYTES;
        uint32_t a[2][4];
        ldsm4(a[0], abuf + aOff[0]);
        ldsm4(a[1], abuf + aOff[1]);
#pragma unroll
        for (int fp = 0; fp < 4; fp++) {
            uint32_t b[4];
            ldsm4(b, bbuf + bOff[fp]);
            mma_f16(acc[0][2 * fp],     a[0], b[0], b[1]);
            mma_f16(acc[1][2 * fp],     a[1], b[0], b[1]);
            mma_f16(acc[0][2 * fp + 1], a[0], b[2], b[3]);
            mma_f16(acc[1][2 * fp + 1], a[1], b[2], b[3]);
        }
        if (t + 1 < T) {
            char* aB = smem + ABUF_OFF + ((t + 1) & 1) * BUFBYTES;
            char* bB = smem + BBUF_OFF + ((t + 1) & 1) * BUFBYTES;
            *(uint4*)(aB + wOff) = pack_h8(ra0, ra1);
            *(uint4*)(bB + wOff) = pack_h8(rb0, rb1);
        }
        __syncthreads();
    }

#pragma unroll
    for (int mf = 0; mf < 2; mf++) {
#pragma unroll
        for (int half = 0; half < 2; half++) {
            int rt = wm * 32 + mf * 16 + half * 8 + lr;
            int m = m0 + rt;
            if (GATHER != 0 && m >= Mv) continue;
            int orow = sslot[rt];
            float sc = (EPI == 1) ? d_gw[orow] : 0.f;
#pragma unroll
            for (int f = 0; f < 8; f++) {
                int nb = wn * 64 + 8 * f + 2 * lc;
                float c0 = acc[mf][f][half * 2 + 0] + sBB[nb];
                float c1 = acc[mf][f][half * 2 + 1] + sBB[nb + 1];
                if (EPI == 1) {
                    *(float2*)(Out + (size_t)orow * ldo + n0 + nb) =
                        make_float2(c0 * sc, c1 * sc);
                } else if (EPI == 2) {
                    const float* y0 = d_ypart + (size_t)(2 * m) * DMODEL + n0 + nb;
                    const float* y1 = y0 + DMODEL;
                    float2 a2 = *(const float2*)y0;
                    float2 b2 = *(const float2*)y1;
                    *(float2*)(Out + (size_t)m * ldo + n0 + nb) =
                        make_float2(c0 + a2.x + b2.x, c1 + a2.y + b2.y);
                } else if (EPI == 3) {
                    *(float2*)(Out + (size_t)orow * ldo + n0 + nb) = make_float2(c0, c1);
                } else { // EPI == 4: fused SwiGLU (g from Aux, u = acc+bias)
                    float2 g2 = *(const float2*)(Aux + (size_t)orow * ldo + n0 + nb);
                    float h0 = g2.x * fsigmoid(g2.x) * c0;
                    float h1 = g2.y * fsigmoid(g2.y) * c1;
                    *(float2*)(Out + (size_t)orow * ldo + n0 + nb) = make_float2(h0, h1);
                }
            }
        }
    }
}

// ---------------- launch ----------------
extern "C" void kernel_launch(void* const* d_in, const int* in_sizes, int n_in,
                              void* d_out, int out_size)
{
    const float* x   = (const float*)d_in[0];
    const float* gw  = (const float*)d_in[1];
    const float* eb  = (const float*)d_in[2];
    const float* w1  = (const float*)d_in[3];
    const float* b1  = (const float*)d_in[4];
    const float* w3  = (const float*)d_in[5];
    const float* b3  = (const float*)d_in[6];
    const float* w2  = (const float*)d_in[7];
    const float* b2  = (const float*)d_in[8];
    const float* sw1 = (const float*)d_in[9];
    const float* sb1 = (const float*)d_in[10];
    const float* sw3 = (const float*)d_in[11];
    const float* sb3 = (const float*)d_in[12];
    const float* sw2 = (const float*)d_in[13];
    const float* sb2 = (const float*)d_in[14];
    float* out = (float*)d_out;

    float* g1_p; cudaGetSymbolAddress((void**)&g1_p, d_g1);
    float* h_p;  cudaGetSymbolAddress((void**)&h_p,  d_h);
    float* hs_p; cudaGetSymbolAddress((void**)&hs_p, d_hs);
    float* yp_p; cudaGetSymbolAddress((void**)&yp_p, d_ypart);

    cudaFuncSetAttribute(gemm128<1,3>, cudaFuncAttributeMaxDynamicSharedMemorySize, SMEM_TOTAL);
    cudaFuncSetAttribute(gemm128<1,4>, cudaFuncAttributeMaxDynamicSharedMemorySize, SMEM_TOTAL);
    cudaFuncSetAttribute(gemm128<2,1>, cudaFuncAttributeMaxDynamicSharedMemorySize, SMEM_TOTAL);
    cudaFuncSetAttribute(gemm128<0,3>, cudaFuncAttributeMaxDynamicSharedMemorySize, SMEM_TOTAL);
    cudaFuncSetAttribute(gemm128<0,4>, cudaFuncAttributeMaxDynamicSharedMemorySize, SMEM_TOTAL);
    cudaFuncSetAttribute(gemm128<0,2>, cudaFuncAttributeMaxDynamicSharedMemorySize, SMEM_TOTAL);

    zero_cnt_kernel<<<1, 32>>>();
    gate_kernel<<<(NTOK * 32) / 256, 256>>>(x, gw, eb);

    // routed stage 1a: g1 = x@W1^T + b1 (gather token rows), N=512, K=1024
    gemm128<1,3><<<dim3(DFFE / 128, NTOK / 128, NEXP), 256, SMEM_TOTAL>>>(
        x, w1, b1, g1_p, nullptr, DMODEL, DFFE, DFFE);
    // routed stage 1b: h = silu(g1) * (x@W3^T + b3)  (fused SwiGLU)
    gemm128<1,4><<<dim3(DFFE / 128, NTOK / 128, NEXP), 256, SMEM_TOTAL>>>(
        x, w3, b3, h_p, g1_p, DMODEL, DFFE, DFFE);
    // routed stage 2: ypart[slot] = (h@W2^T + b2) * gate_w, N=1024, K=512
    gemm128<2,1><<<dim3(DMODEL / 128, NTOK / 128, NEXP), 256, SMEM_TOTAL>>>(
        h_p, w2, b2, yp_p, nullptr, DFFE, DMODEL, DMODEL);

    // shared stage 1a/1b: dense, N=1024, K=1024
    gemm128<0,3><<<dim3(DFFS / 128, NTOK / 128, 1), 256, SMEM_TOTAL>>>(
        x, sw1, sb1, g1_p, nullptr, DMODEL, DFFS, DFFS);
    gemm128<0,4><<<dim3(DFFS / 128, NTOK / 128, 1), 256, SMEM_TOTAL>>>(
        x, sw3, sb3, hs_p, g1_p, DMODEL, DFFS, DFFS);

    // shared stage 2 + combine: out = hs@sW2^T + sb2 + ypart[2m] + ypart[2m+1]
    gemm128<0,2><<<dim3(DMODEL / 128, NTOK / 128, 1), 256, SMEM_TOTAL>>>(
        hs_p, sw2, sb2, out, nullptr, DMODEL, DMODEL, DMODEL);
}

// round 9
// speedup vs baseline: 1.8850x; 1.5699x over previous
#include <cuda_runtime.h>
#include <cuda_fp16.h>
#include <cstdint>
#include <math.h>

#define NTOK   8192
#define DMODEL 1024
#define DFFE   512
#define NEXP   16
#define DFFS   1024

// ---------------- scratch (device globals; no allocations) ----------------
__device__ int   d_cnt[NEXP];
__device__ int   d_lists[NEXP * NTOK];
__device__ float d_gw[2 * NTOK];
__device__ float d_g1[(size_t)2 * NTOK * DFFS];        // biased g1 (fp32)
__device__ float d_ypart[(size_t)2 * NTOK * DMODEL];   // routed partials (fp32)
// fp16 operands
__device__ __half d_hx [(size_t)NTOK * DMODEL];
__device__ __half d_w1h[(size_t)NEXP * DFFE * DMODEL];
__device__ __half d_w3h[(size_t)NEXP * DFFE * DMODEL];
__device__ __half d_w2h[(size_t)NEXP * DMODEL * DFFE];
__device__ __half d_sw1h[(size_t)DFFS * DMODEL];
__device__ __half d_sw3h[(size_t)DFFS * DMODEL];
__device__ __half d_sw2h[(size_t)DMODEL * DFFS];
__device__ __half d_h [(size_t)2 * NTOK * DFFE];       // routed hidden (fp16)
__device__ __half d_hs[(size_t)NTOK * DFFS];           // shared hidden (fp16)

__device__ __forceinline__ float fsigmoid(float v) { return 1.f / (1.f + __expf(-v)); }
__device__ __forceinline__ uint32_t smem_u32(const void* p) {
    uint32_t a;
    asm("{ .reg .u64 t; cvta.to.shared.u64 t, %1; cvt.u32.u64 %0, t; }" : "=r"(a) : "l"(p));
    return a;
}
__device__ __forceinline__ void mma_f16(float* c, const uint32_t* a, uint32_t b0, uint32_t b1) {
    asm volatile("mma.sync.aligned.m16n8k16.row.col.f32.f16.f16.f32 "
        "{%0,%1,%2,%3}, {%4,%5,%6,%7}, {%8,%9}, {%0,%1,%2,%3};"
        : "+f"(c[0]), "+f"(c[1]), "+f"(c[2]), "+f"(c[3])
        : "r"(a[0]), "r"(a[1]), "r"(a[2]), "r"(a[3]), "r"(b0), "r"(b1));
}
__device__ __forceinline__ void ldsm4(uint32_t* r, uint32_t addr) {
    asm volatile("ldmatrix.sync.aligned.m8n8.x4.shared.b16 {%0,%1,%2,%3}, [%4];"
        : "=r"(r[0]), "=r"(r[1]), "=r"(r[2]), "=r"(r[3]) : "r"(addr));
}
__device__ __forceinline__ void cp_async16(uint32_t dst, const void* src) {
    asm volatile("cp.async.cg.shared.global [%0], [%1], 16;" :: "r"(dst), "l"(src));
}
__device__ __forceinline__ uint4 pack_h8(float4 u, float4 v) {
    uint4 o;
    half2 h0 = __floats2half2_rn(u.x, u.y);
    half2 h1 = __floats2half2_rn(u.z, u.w);
    half2 h2 = __floats2half2_rn(v.x, v.y);
    half2 h3 = __floats2half2_rn(v.z, v.w);
    o.x = *(uint32_t*)&h0; o.y = *(uint32_t*)&h1;
    o.z = *(uint32_t*)&h2; o.w = *(uint32_t*)&h3;
    return o;
}

// ---------------- smem layout ----------------
// BK=32 halfs (64B/row data), row stride 80B -> LDSM rows mod 128:
// {0,80,32,112,64,16,96,48}: conflict-free; 16B aligned for cp.async.
#define BK       32
#define RS       80
#define NSTAGE   4
#define BUFBYTES (128 * RS)                    // 10240
#define ABUF_OFF 0
#define BBUF_OFF (NSTAGE * BUFBYTES)           // 40960
#define SLOT_OFF (2 * NSTAGE * BUFBYTES)       // 81920
#define BIAS_OFF (SLOT_OFF + 512)
#define SMEM_TOTAL (BIAS_OFF + 512)            // 82944

// ---------------- small kernels ----------------
__global__ void zero_cnt_kernel() {
    if (threadIdx.x < NEXP) d_cnt[threadIdx.x] = 0;
}

__global__ void f2h_kernel(const float* __restrict__ src, __half* __restrict__ dst) {
    size_t i = ((size_t)blockIdx.x * blockDim.x + threadIdx.x) * 8;
    float4 a = *(const float4*)(src + i);
    float4 b = *(const float4*)(src + i + 4);
    *(uint4*)(dst + i) = pack_h8(a, b);
}

__global__ void gate_kernel(const float* __restrict__ x,
                            const float* __restrict__ gw,
                            const float* __restrict__ ebias)
{
    int warp = (blockIdx.x * blockDim.x + threadIdx.x) >> 5;
    int lane = threadIdx.x & 31;
    if (warp >= NTOK) return;
    const float* xr = x + (size_t)warp * DMODEL;
    float xv[32];
#pragma unroll
    for (int j = 0; j < 32; j++) xv[j] = xr[lane + 32 * j];
    float logits[NEXP];
#pragma unroll
    for (int e = 0; e < NEXP; e++) {
        const float* wr = gw + e * DMODEL;
        float acc = 0.f;
#pragma unroll
        for (int j = 0; j < 32; j++) acc += xv[j] * wr[lane + 32 * j];
#pragma unroll
        for (int o = 16; o > 0; o >>= 1) acc += __shfl_xor_sync(0xffffffffu, acc, o);
        logits[e] = acc;
    }
    if (lane == 0) {
        int i0 = -1, i1 = -1;
        float v0 = -INFINITY, v1 = -INFINITY;
#pragma unroll
        for (int e = 0; e < NEXP; e++) {
            float b = logits[e] + ebias[e];
            if (b > v0) { v1 = v0; i1 = i0; v0 = b; i0 = e; }
            else if (b > v1) { v1 = b; i1 = e; }
        }
        float s0 = fsigmoid(logits[i0]);
        float s1 = fsigmoid(logits[i1]);
        float inv = 1.f / (s0 + s1 + 1e-10f);
        int p0 = atomicAdd(&d_cnt[i0], 1);
        d_lists[i0 * NTOK + p0] = warp * 2 + 0;
        d_gw[warp * 2 + 0] = s0 * inv;
        int p1 = atomicAdd(&d_cnt[i1], 1);
        d_lists[i1 * NTOK + p1] = warp * 2 + 1;
        d_gw[warp * 2 + 1] = s1 * inv;
    }
}

// ---------------- unified 128x128x32 fp16 GEMM, cp.async 4-stage ----------------
// GATHER: 0 dense, 1 gather token (slot>>1), 2 gather slot
// EPI: 1 (acc+b)*gw -> ypart(f32); 2 acc+b+ypart2 -> out(f32);
//      3 acc+b -> g1(f32);        4 silu(Aux)* (acc+b) -> h(f16)
template<int GATHER, int EPI>
__global__ void __launch_bounds__(256, 2)
gemm128(const __half* __restrict__ A, const __half* __restrict__ Wb,
        const float* __restrict__ bb, void* __restrict__ OutV,
        const float* __restrict__ Aux, int K, int NW, int ldo)
{
    int e  = blockIdx.z;
    int m0 = blockIdx.y * 128;
    int n0 = blockIdx.x * 128;
    int Mv = NTOK;
    const int* list = d_lists + e * NTOK;
    if (GATHER != 0) { Mv = d_cnt[e]; if (m0 >= Mv) return; }
    const __half* W = Wb + (size_t)e * NW * K;

    extern __shared__ char smem[];
    uint32_t sbase = smem_u32(smem);
    int*   sslot = (int*)(smem + SLOT_OFF);
    float* sBB   = (float*)(smem + BIAS_OFF);

    int tid = threadIdx.x;
    if (tid < 128) {
        int m = m0 + tid;
        sslot[tid] = (GATHER != 0) ? list[m < Mv ? m : Mv - 1] : m;
    } else {
        sBB[tid - 128] = bb[(size_t)e * NW + n0 + (tid - 128)];
    }
    __syncthreads();

    // cp.async writer: 2 x 16B per matrix per tile per thread
    const __half* aSrc[2]; const __half* bSrc[2]; uint32_t dstOff[2];
#pragma unroll
    for (int i = 0; i < 2; i++) {
        int idx = tid + i * 256;            // 0..511
        int row = idx >> 2, c = idx & 3;    // 4 x 16B chunks per 64B row
        int slot = sslot[row];
        int ar = (GATHER == 1) ? (slot >> 1) : slot;
        aSrc[i] = A + (size_t)ar * K + c * 8;
        bSrc[i] = W + (size_t)(n0 + row) * K + c * 8;
        dstOff[i] = (uint32_t)(row * RS + c * 16);
    }

    int wid = tid >> 5, lane = tid & 31;
    int wm = wid & 3, wn = wid >> 2;
    int lr = lane >> 2, lc = lane & 3;
    int mat = lane >> 3, rr = lane & 7;

    uint32_t aOff[2], bOff[4];
#pragma unroll
    for (int mf = 0; mf < 2; mf++)
        aOff[mf] = (uint32_t)((wm * 32 + mf * 16 + (mat & 1) * 8 + rr) * RS + (mat >> 1) * 16);
#pragma unroll
    for (int fp = 0; fp < 4; fp++)
        bOff[fp] = (uint32_t)((wn * 64 + fp * 16 + (mat >> 1) * 8 + rr) * RS + (mat & 1) * 16);

    float acc[2][8][4] = {};

    int T = K / BK;

    auto issue_tile = [&](int t) {
        int buf = t & (NSTAGE - 1);
        uint32_t aB = sbase + ABUF_OFF + buf * BUFBYTES;
        uint32_t bB = sbase + BBUF_OFF + buf * BUFBYTES;
        int k0 = t * BK;
#pragma unroll
        for (int i = 0; i < 2; i++) {
            cp_async16(aB + dstOff[i], aSrc[i] + k0);
            cp_async16(bB + dstOff[i], bSrc[i] + k0);
        }
        asm volatile("cp.async.commit_group;" ::: "memory");
    };

    issue_tile(0);
    issue_tile(1);
    issue_tile(2);

    for (int t = 0; t < T; t++) {
        asm volatile("cp.async.wait_group 2;" ::: "memory");
        __syncthreads();
        uint32_t abuf = sbase + ABUF_OFF + (t & (NSTAGE - 1)) * BUFBYTES;
        uint32_t bbuf = sbase + BBUF_OFF + (t & (NSTAGE - 1)) * BUFBYTES;
#pragma unroll
        for (int kk = 0; kk < 2; kk++) {
            uint32_t koff = kk * 32;
            uint32_t a[2][4];
            ldsm4(a[0], abuf + aOff[0] + koff);
            ldsm4(a[1], abuf + aOff[1] + koff);
#pragma unroll
            for (int fp = 0; fp < 4; fp++) {
                uint32_t b[4];
                ldsm4(b, bbuf + bOff[fp] + koff);
                mma_f16(acc[0][2 * fp],     a[0], b[0], b[1]);
                mma_f16(acc[1][2 * fp],     a[1], b[0], b[1]);
                mma_f16(acc[0][2 * fp + 1], a[0], b[2], b[3]);
                mma_f16(acc[1][2 * fp + 1], a[1], b[2], b[3]);
            }
        }
        // EXACTLY one commit_group per iteration: keeps wait_group 2 semantics
        // valid through the pipeline drain (tail tiles T-2, T-1 were racy before).
        if (t + 3 < T) {
            issue_tile(t + 3);
        } else {
            asm volatile("cp.async.commit_group;" ::: "memory");
        }
    }

#pragma unroll
    for (int mf = 0; mf < 2; mf++) {
#pragma unroll
        for (int half = 0; half < 2; half++) {
            int rt = wm * 32 + mf * 16 + half * 8 + lr;
            int m = m0 + rt;
            if (GATHER != 0 && m >= Mv) continue;
            int orow = sslot[rt];
            float sc = (EPI == 1) ? d_gw[orow] : 0.f;
#pragma unroll
            for (int f = 0; f < 8; f++) {
                int nb = wn * 64 + 8 * f + 2 * lc;
                float c0 = acc[mf][f][half * 2 + 0] + sBB[nb];
                float c1 = acc[mf][f][half * 2 + 1] + sBB[nb + 1];
                if (EPI == 1) {
                    float* O = (float*)OutV;
                    *(float2*)(O + (size_t)orow * ldo + n0 + nb) =
                        make_float2(c0 * sc, c1 * sc);
                } else if (EPI == 2) {
                    const float* y0 = d_ypart + (size_t)(2 * m) * DMODEL + n0 + nb;
                    const float* y1 = y0 + DMODEL;
                    float2 a2 = *(const float2*)y0;
                    float2 b2 = *(const float2*)y1;
                    float* O = (float*)OutV;
                    *(float2*)(O + (size_t)m * ldo + n0 + nb) =
                        make_float2(c0 + a2.x + b2.x, c1 + a2.y + b2.y);
                } else if (EPI == 3) {
                    float* O = (float*)OutV;
                    *(float2*)(O + (size_t)orow * ldo + n0 + nb) = make_float2(c0, c1);
                } else { // EPI == 4: h = silu(g) * u -> fp16
                    float2 g2 = *(const float2*)(Aux + (size_t)orow * ldo + n0 + nb);
                    float h0 = g2.x * fsigmoid(g2.x) * c0;
                    float h1 = g2.y * fsigmoid(g2.y) * c1;
                    __half* O = (__half*)OutV;
                    *(half2*)(O + (size_t)orow * ldo + n0 + nb) = __floats2half2_rn(h0, h1);
                }
            }
        }
    }
}

// ---------------- launch ----------------
extern "C" void kernel_launch(void* const* d_in, const int* in_sizes, int n_in,
                              void* d_out, int out_size)
{
    const float* x   = (const float*)d_in[0];
    const float* gw  = (const float*)d_in[1];
    const float* eb  = (const float*)d_in[2];
    const float* w1  = (const float*)d_in[3];
    const float* b1  = (const float*)d_in[4];
    const float* w3  = (const float*)d_in[5];
    const float* b3  = (const float*)d_in[6];
    const float* w2  = (const float*)d_in[7];
    const float* b2  = (const float*)d_in[8];
    const float* sw1 = (const float*)d_in[9];
    const float* sb1 = (const float*)d_in[10];
    const float* sw3 = (const float*)d_in[11];
    const float* sb3 = (const float*)d_in[12];
    const float* sw2 = (const float*)d_in[13];
    const float* sb2 = (const float*)d_in[14];
    float* out = (float*)d_out;

    float*  g1_p;  cudaGetSymbolAddress((void**)&g1_p,  d_g1);
    float*  yp_p;  cudaGetSymbolAddress((void**)&yp_p,  d_ypart);
    __half* hx_p;  cudaGetSymbolAddress((void**)&hx_p,  d_hx);
    __half* w1h_p; cudaGetSymbolAddress((void**)&w1h_p, d_w1h);
    __half* w3h_p; cudaGetSymbolAddress((void**)&w3h_p, d_w3h);
    __half* w2h_p; cudaGetSymbolAddress((void**)&w2h_p, d_w2h);
    __half* sw1h_p; cudaGetSymbolAddress((void**)&sw1h_p, d_sw1h);
    __half* sw3h_p; cudaGetSymbolAddress((void**)&sw3h_p, d_sw3h);
    __half* sw2h_p; cudaGetSymbolAddress((void**)&sw2h_p, d_sw2h);
    __half* h_p;   cudaGetSymbolAddress((void**)&h_p,   d_h);
    __half* hs_p;  cudaGetSymbolAddress((void**)&hs_p,  d_hs);

    cudaFuncSetAttribute(gemm128<1,3>, cudaFuncAttributeMaxDynamicSharedMemorySize, SMEM_TOTAL);
    cudaFuncSetAttribute(gemm128<1,4>, cudaFuncAttributeMaxDynamicSharedMemorySize, SMEM_TOTAL);
    cudaFuncSetAttribute(gemm128<2,1>, cudaFuncAttributeMaxDynamicSharedMemorySize, SMEM_TOTAL);
    cudaFuncSetAttribute(gemm128<0,3>, cudaFuncAttributeMaxDynamicSharedMemorySize, SMEM_TOTAL);
    cudaFuncSetAttribute(gemm128<0,4>, cudaFuncAttributeMaxDynamicSharedMemorySize, SMEM_TOTAL);
    cudaFuncSetAttribute(gemm128<0,2>, cudaFuncAttributeMaxDynamicSharedMemorySize, SMEM_TOTAL);

    zero_cnt_kernel<<<1, 32>>>();
    gate_kernel<<<(NTOK * 32) / 256, 256>>>(x, gw, eb);

    // fp32 -> fp16 operand conversion
    const size_t NX  = (size_t)NTOK * DMODEL;                 // 8388608
    const size_t NW13 = (size_t)NEXP * DFFE * DMODEL;         // 8388608
    const size_t NSW  = (size_t)DFFS * DMODEL;                // 1048576
    f2h_kernel<<<NX   / 2048, 256>>>(x,   hx_p);
    f2h_kernel<<<NW13 / 2048, 256>>>(w1,  w1h_p);
    f2h_kernel<<<NW13 / 2048, 256>>>(w3,  w3h_p);
    f2h_kernel<<<NW13 / 2048, 256>>>(w2,  w2h_p);
    f2h_kernel<<<NSW  / 2048, 256>>>(sw1, sw1h_p);
    f2h_kernel<<<NSW  / 2048, 256>>>(sw3, sw3h_p);
    f2h_kernel<<<NSW  / 2048, 256>>>(sw2, sw2h_p);

    // routed stage 1a: g1 = x@W1^T + b1 (gather tokens), N=512, K=1024
    gemm128<1,3><<<dim3(DFFE / 128, NTOK / 128, NEXP), 256, SMEM_TOTAL>>>(
        hx_p, w1h_p, b1, g1_p, nullptr, DMODEL, DFFE, DFFE);
    // routed stage 1b: h = silu(g1) * (x@W3^T + b3) -> fp16
    gemm128<1,4><<<dim3(DFFE / 128, NTOK / 128, NEXP), 256, SMEM_TOTAL>>>(
        hx_p, w3h_p, b3, h_p, g1_p, DMODEL, DFFE, DFFE);
    // routed stage 2: ypart[slot] = (h@W2^T + b2) * gate_w, N=1024, K=512
    gemm128<2,1><<<dim3(DMODEL / 128, NTOK / 128, NEXP), 256, SMEM_TOTAL>>>(
        h_p, w2h_p, b2, yp_p, nullptr, DFFE, DMODEL, DMODEL);

    // shared stage 1a/1b: dense, N=1024, K=1024
    gemm128<0,3><<<dim3(DFFS / 128, NTOK / 128, 1), 256, SMEM_TOTAL>>>(
        hx_p, sw1h_p, sb1, g1_p, nullptr, DMODEL, DFFS, DFFS);
    gemm128<0,4><<<dim3(DFFS / 128, NTOK / 128, 1), 256, SMEM_TOTAL>>>(
        hx_p, sw3h_p, sb3, hs_p, g1_p, DMODEL, DFFS, DFFS);

    // shared stage 2 + combine: out = hs@sW2^T + sb2 + ypart[2m] + ypart[2m+1]
    gemm128<0,2><<<dim3(DMODEL / 128, NTOK / 128, 1), 256, SMEM_TOTAL>>>(
        hs_p, sw2h_p, sb2, out, nullptr, DMODEL, DMODEL, DMODEL);
}

// round 10
// speedup vs baseline: 2.1080x; 1.1183x over previous
#include <cuda_runtime.h>
#include <cuda_fp16.h>
#include <cstdint>
#include <math.h>

#define NTOK   8192
#define DMODEL 1024
#define DFFE   512
#define NEXP   16
#define DFFS   1024

// ---------------- scratch (device globals; no allocations) ----------------
__device__ int   d_cnt[NEXP];
__device__ int   d_lists[NEXP * NTOK];
__device__ float d_gw[2 * NTOK];
__device__ float d_g1[(size_t)2 * NTOK * DFFS];        // biased g1 (fp32)
__device__ float d_ypart[(size_t)2 * NTOK * DMODEL];   // routed partials (fp32)
// fp16 operands
__device__ __half d_hx [(size_t)NTOK * DMODEL];
__device__ __half d_w1h[(size_t)NEXP * DFFE * DMODEL];
__device__ __half d_w3h[(size_t)NEXP * DFFE * DMODEL];
__device__ __half d_w2h[(size_t)NEXP * DMODEL * DFFE];
__device__ __half d_sw1h[(size_t)DFFS * DMODEL];
__device__ __half d_sw3h[(size_t)DFFS * DMODEL];
__device__ __half d_sw2h[(size_t)DMODEL * DFFS];
__device__ __half d_h [(size_t)2 * NTOK * DFFE];       // routed hidden (fp16)
__device__ __half d_hs[(size_t)NTOK * DFFS];           // shared hidden (fp16)

__device__ __forceinline__ float fsigmoid(float v) { return 1.f / (1.f + __expf(-v)); }
__device__ __forceinline__ uint32_t smem_u32(const void* p) {
    uint32_t a;
    asm("{ .reg .u64 t; cvta.to.shared.u64 t, %1; cvt.u32.u64 %0, t; }" : "=r"(a) : "l"(p));
    return a;
}
__device__ __forceinline__ void mma_f16(float* c, const uint32_t* a, uint32_t b0, uint32_t b1) {
    asm volatile("mma.sync.aligned.m16n8k16.row.col.f32.f16.f16.f32 "
        "{%0,%1,%2,%3}, {%4,%5,%6,%7}, {%8,%9}, {%0,%1,%2,%3};"
        : "+f"(c[0]), "+f"(c[1]), "+f"(c[2]), "+f"(c[3])
        : "r"(a[0]), "r"(a[1]), "r"(a[2]), "r"(a[3]), "r"(b0), "r"(b1));
}
__device__ __forceinline__ void ldsm4(uint32_t* r, uint32_t addr) {
    asm volatile("ldmatrix.sync.aligned.m8n8.x4.shared.b16 {%0,%1,%2,%3}, [%4];"
        : "=r"(r[0]), "=r"(r[1]), "=r"(r[2]), "=r"(r[3]) : "r"(addr));
}
__device__ __forceinline__ void cp_async16(uint32_t dst, const void* src) {
    asm volatile("cp.async.cg.shared.global [%0], [%1], 16;" :: "r"(dst), "l"(src));
}
__device__ __forceinline__ uint4 pack_h8(float4 u, float4 v) {
    uint4 o;
    half2 h0 = __floats2half2_rn(u.x, u.y);
    half2 h1 = __floats2half2_rn(u.z, u.w);
    half2 h2 = __floats2half2_rn(v.x, v.y);
    half2 h3 = __floats2half2_rn(v.z, v.w);
    o.x = *(uint32_t*)&h0; o.y = *(uint32_t*)&h1;
    o.z = *(uint32_t*)&h2; o.w = *(uint32_t*)&h3;
    return o;
}

// ---------------- smem layout ----------------
// BK=64 halfs (128B data/row), row stride 144B.
// LDSM: 8 rows x 36 words (mod 32) -> each row's 4 words hit a distinct
// bank quad; all 32 banks covered exactly once: conflict-free. 16B aligned.
#define BK       64
#define RS       144
#define NSTAGE   3
#define BUFBYTES (128 * RS)                    // 18432
#define ABUF_OFF 0
#define BBUF_OFF (NSTAGE * BUFBYTES)           // 55296
#define SLOT_OFF (2 * NSTAGE * BUFBYTES)       // 110592
#define BIAS_OFF (SLOT_OFF + 512)
#define SMEM_TOTAL (BIAS_OFF + 512)            // 111616

// ---------------- small kernels ----------------
__global__ void zero_cnt_kernel() {
    if (threadIdx.x < NEXP) d_cnt[threadIdx.x] = 0;
}

// merged fp32->fp16 conversion over 7 segments
struct F2HArgs {
    const float* src[7];
    __half*      dst[7];
    int          blk_end[7];   // cumulative block counts (2048 elems per block)
};
__global__ void f2h_all_kernel(F2HArgs args) {
    int b = blockIdx.x;
    int seg = 0;
#pragma unroll
    for (int s = 0; s < 7; s++) if (b >= args.blk_end[s]) seg = s + 1;
    int b0 = (seg == 0) ? 0 : args.blk_end[seg - 1];
    size_t i = ((size_t)(b - b0) * blockDim.x + threadIdx.x) * 8;
    const float* src = args.src[seg];
    __half* dst = args.dst[seg];
    float4 a = *(const float4*)(src + i);
    float4 v = *(const float4*)(src + i + 4);
    *(uint4*)(dst + i) = pack_h8(a, v);
}

__global__ void gate_kernel(const float* __restrict__ x,
                            const float* __restrict__ gw,
                            const float* __restrict__ ebias)
{
    int warp = (blockIdx.x * blockDim.x + threadIdx.x) >> 5;
    int lane = threadIdx.x & 31;
    if (warp >= NTOK) return;
    const float* xr = x + (size_t)warp * DMODEL;
    float xv[32];
#pragma unroll
    for (int j = 0; j < 32; j++) xv[j] = xr[lane + 32 * j];
    float logits[NEXP];
#pragma unroll
    for (int e = 0; e < NEXP; e++) {
        const float* wr = gw + e * DMODEL;
        float acc = 0.f;
#pragma unroll
        for (int j = 0; j < 32; j++) acc += xv[j] * wr[lane + 32 * j];
#pragma unroll
        for (int o = 16; o > 0; o >>= 1) acc += __shfl_xor_sync(0xffffffffu, acc, o);
        logits[e] = acc;
    }
    if (lane == 0) {
        int i0 = -1, i1 = -1;
        float v0 = -INFINITY, v1 = -INFINITY;
#pragma unroll
        for (int e = 0; e < NEXP; e++) {
            float b = logits[e] + ebias[e];
            if (b > v0) { v1 = v0; i1 = i0; v0 = b; i0 = e; }
            else if (b > v1) { v1 = b; i1 = e; }
        }
        float s0 = fsigmoid(logits[i0]);
        float s1 = fsigmoid(logits[i1]);
        float inv = 1.f / (s0 + s1 + 1e-10f);
        int p0 = atomicAdd(&d_cnt[i0], 1);
        d_lists[i0 * NTOK + p0] = warp * 2 + 0;
        d_gw[warp * 2 + 0] = s0 * inv;
        int p1 = atomicAdd(&d_cnt[i1], 1);
        d_lists[i1 * NTOK + p1] = warp * 2 + 1;
        d_gw[warp * 2 + 1] = s1 * inv;
    }
}

// ---------------- unified 128x128x64 fp16 GEMM, cp.async 3-stage ----------------
// GATHER: 0 dense, 1 gather token (slot>>1), 2 gather slot
// EPI: 1 (acc+b)*gw -> ypart(f32); 2 acc+b+ypart2 -> out(f32);
//      3 acc+b -> g1(f32);        4 silu(Aux)* (acc+b) -> h(f16)
template<int GATHER, int EPI>
__global__ void __launch_bounds__(256, 2)
gemm128(const __half* __restrict__ A, const __half* __restrict__ Wb,
        const float* __restrict__ bb, void* __restrict__ OutV,
        const float* __restrict__ Aux, int K, int NW, int ldo)
{
    int e  = blockIdx.z;
    int m0 = blockIdx.y * 128;
    int n0 = blockIdx.x * 128;
    int Mv = NTOK;
    const int* list = d_lists + e * NTOK;
    if (GATHER != 0) { Mv = d_cnt[e]; if (m0 >= Mv) return; }
    const __half* W = Wb + (size_t)e * NW * K;

    extern __shared__ char smem[];
    uint32_t sbase = smem_u32(smem);
    int*   sslot = (int*)(smem + SLOT_OFF);
    float* sBB   = (float*)(smem + BIAS_OFF);

    int tid = threadIdx.x;
    if (tid < 128) {
        int m = m0 + tid;
        sslot[tid] = (GATHER != 0) ? list[m < Mv ? m : Mv - 1] : m;
    } else {
        sBB[tid - 128] = bb[(size_t)e * NW + n0 + (tid - 128)];
    }
    __syncthreads();

    // cp.async writer: 4 x 16B per matrix per tile per thread (128 rows x 128B)
    const __half* aSrc[4]; const __half* bSrc[4]; uint32_t dstOff[4];
#pragma unroll
    for (int i = 0; i < 4; i++) {
        int idx = tid + i * 256;            // 0..1023
        int row = idx >> 3, c = idx & 7;    // 8 x 16B chunks per 128B row
        int slot = sslot[row];
        int ar = (GATHER == 1) ? (slot >> 1) : slot;
        aSrc[i] = A + (size_t)ar * K + c * 8;
        bSrc[i] = W + (size_t)(n0 + row) * K + c * 8;
        dstOff[i] = (uint32_t)(row * RS + c * 16);
    }

    int wid = tid >> 5, lane = tid & 31;
    int wm = wid & 3, wn = wid >> 2;
    int lr = lane >> 2, lc = lane & 3;
    int mat = lane >> 3, rr = lane & 7;

    uint32_t aOff[2], bOff[4];
#pragma unroll
    for (int mf = 0; mf < 2; mf++)
        aOff[mf] = (uint32_t)((wm * 32 + mf * 16 + (mat & 1) * 8 + rr) * RS + (mat >> 1) * 16);
#pragma unroll
    for (int fp = 0; fp < 4; fp++)
        bOff[fp] = (uint32_t)((wn * 64 + fp * 16 + (mat >> 1) * 8 + rr) * RS + (mat & 1) * 16);

    float acc[2][8][4] = {};

    int T = K / BK;

    auto issue_tile = [&](int t) {
        int buf = t % NSTAGE;
        uint32_t aB = sbase + ABUF_OFF + buf * BUFBYTES;
        uint32_t bB = sbase + BBUF_OFF + buf * BUFBYTES;
        int k0 = t * BK;
#pragma unroll
        for (int i = 0; i < 4; i++) {
            cp_async16(aB + dstOff[i], aSrc[i] + k0);
            cp_async16(bB + dstOff[i], bSrc[i] + k0);
        }
        asm volatile("cp.async.commit_group;" ::: "memory");
    };

    issue_tile(0);
    issue_tile(1);

    for (int t = 0; t < T; t++) {
        asm volatile("cp.async.wait_group 1;" ::: "memory");
        __syncthreads();
        uint32_t abuf = sbase + ABUF_OFF + (t % NSTAGE) * BUFBYTES;
        uint32_t bbuf = sbase + BBUF_OFF + (t % NSTAGE) * BUFBYTES;
#pragma unroll
        for (int kk = 0; kk < 4; kk++) {
            uint32_t koff = kk * 32;
            uint32_t a[2][4];
            ldsm4(a[0], abuf + aOff[0] + koff);
            ldsm4(a[1], abuf + aOff[1] + koff);
#pragma unroll
            for (int fp = 0; fp < 4; fp++) {
                uint32_t b[4];
                ldsm4(b, bbuf + bOff[fp] + koff);
                mma_f16(acc[0][2 * fp],     a[0], b[0], b[1]);
                mma_f16(acc[1][2 * fp],     a[1], b[0], b[1]);
                mma_f16(acc[0][2 * fp + 1], a[0], b[2], b[3]);
                mma_f16(acc[1][2 * fp + 1], a[1], b[2], b[3]);
            }
        }
        // exactly one commit per iteration (keeps wait_group 1 valid in drain)
        if (t + 2 < T) {
            issue_tile(t + 2);
        } else {
            asm volatile("cp.async.commit_group;" ::: "memory");
        }
    }

#pragma unroll
    for (int mf = 0; mf < 2; mf++) {
#pragma unroll
        for (int half = 0; half < 2; half++) {
            int rt = wm * 32 + mf * 16 + half * 8 + lr;
            int m = m0 + rt;
            if (GATHER != 0 && m >= Mv) continue;
            int orow = sslot[rt];
            float sc = (EPI == 1) ? d_gw[orow] : 0.f;
#pragma unroll
            for (int f = 0; f < 8; f++) {
                int nb = wn * 64 + 8 * f + 2 * lc;
                float c0 = acc[mf][f][half * 2 + 0] + sBB[nb];
                float c1 = acc[mf][f][half * 2 + 1] + sBB[nb + 1];
                if (EPI == 1) {
                    float* O = (float*)OutV;
                    *(float2*)(O + (size_t)orow * ldo + n0 + nb) =
                        make_float2(c0 * sc, c1 * sc);
                } else if (EPI == 2) {
                    const float* y0 = d_ypart + (size_t)(2 * m) * DMODEL + n0 + nb;
                    const float* y1 = y0 + DMODEL;
                    float2 a2 = *(const float2*)y0;
                    float2 b2 = *(const float2*)y1;
                    float* O = (float*)OutV;
                    *(float2*)(O + (size_t)m * ldo + n0 + nb) =
                        make_float2(c0 + a2.x + b2.x, c1 + a2.y + b2.y);
                } else if (EPI == 3) {
                    float* O = (float*)OutV;
                    *(float2*)(O + (size_t)orow * ldo + n0 + nb) = make_float2(c0, c1);
                } else { // EPI == 4: h = silu(g) * u -> fp16
                    float2 g2 = *(const float2*)(Aux + (size_t)orow * ldo + n0 + nb);
                    float h0 = g2.x * fsigmoid(g2.x) * c0;
                    float h1 = g2.y * fsigmoid(g2.y) * c1;
                    __half* O = (__half*)OutV;
                    *(half2*)(O + (size_t)orow * ldo + n0 + nb) = __floats2half2_rn(h0, h1);
                }
            }
        }
    }
}

// ---------------- launch ----------------
extern "C" void kernel_launch(void* const* d_in, const int* in_sizes, int n_in,
                              void* d_out, int out_size)
{
    const float* x   = (const float*)d_in[0];
    const float* gw  = (const float*)d_in[1];
    const float* eb  = (const float*)d_in[2];
    const float* w1  = (const float*)d_in[3];
    const float* b1  = (const float*)d_in[4];
    const float* w3  = (const float*)d_in[5];
    const float* b3  = (const float*)d_in[6];
    const float* w2  = (const float*)d_in[7];
    const float* b2  = (const float*)d_in[8];
    const float* sw1 = (const float*)d_in[9];
    const float* sb1 = (const float*)d_in[10];
    const float* sw3 = (const float*)d_in[11];
    const float* sb3 = (const float*)d_in[12];
    const float* sw2 = (const float*)d_in[13];
    const float* sb2 = (const float*)d_in[14];
    float* out = (float*)d_out;

    float*  g1_p;  cudaGetSymbolAddress((void**)&g1_p,  d_g1);
    float*  yp_p;  cudaGetSymbolAddress((void**)&yp_p,  d_ypart);
    __half* hx_p;  cudaGetSymbolAddress((void**)&hx_p,  d_hx);
    __half* w1h_p; cudaGetSymbolAddress((void**)&w1h_p, d_w1h);
    __half* w3h_p; cudaGetSymbolAddress((void**)&w3h_p, d_w3h);
    __half* w2h_p; cudaGetSymbolAddress((void**)&w2h_p, d_w2h);
    __half* sw1h_p; cudaGetSymbolAddress((void**)&sw1h_p, d_sw1h);
    __half* sw3h_p; cudaGetSymbolAddress((void**)&sw3h_p, d_sw3h);
    __half* sw2h_p; cudaGetSymbolAddress((void**)&sw2h_p, d_sw2h);
    __half* h_p;   cudaGetSymbolAddress((void**)&h_p,   d_h);
    __half* hs_p;  cudaGetSymbolAddress((void**)&hs_p,  d_hs);

    cudaFuncSetAttribute(gemm128<1,3>, cudaFuncAttributeMaxDynamicSharedMemorySize, SMEM_TOTAL);
    cudaFuncSetAttribute(gemm128<1,4>, cudaFuncAttributeMaxDynamicSharedMemorySize, SMEM_TOTAL);
    cudaFuncSetAttribute(gemm128<2,1>, cudaFuncAttributeMaxDynamicSharedMemorySize, SMEM_TOTAL);
    cudaFuncSetAttribute(gemm128<0,3>, cudaFuncAttributeMaxDynamicSharedMemorySize, SMEM_TOTAL);
    cudaFuncSetAttribute(gemm128<0,4>, cudaFuncAttributeMaxDynamicSharedMemorySize, SMEM_TOTAL);
    cudaFuncSetAttribute(gemm128<0,2>, cudaFuncAttributeMaxDynamicSharedMemorySize, SMEM_TOTAL);

    zero_cnt_kernel<<<1, 32>>>();
    gate_kernel<<<(NTOK * 32) / 256, 256>>>(x, gw, eb);

    // merged fp32 -> fp16 conversions (2048 elems per block)
    {
        const int BX  = (int)(((size_t)NTOK * DMODEL) / 2048);        // 4096
        const int BW  = (int)(((size_t)NEXP * DFFE * DMODEL) / 2048); // 4096
        const int BSW = (int)(((size_t)DFFS * DMODEL) / 2048);        // 512
        F2HArgs a;
        a.src[0] = x;   a.dst[0] = hx_p;
        a.src[1] = w1;  a.dst[1] = w1h_p;
        a.src[2] = w3;  a.dst[2] = w3h_p;
        a.src[3] = w2;  a.dst[3] = w2h_p;
        a.src[4] = sw1; a.dst[4] = sw1h_p;
        a.src[5] = sw3; a.dst[5] = sw3h_p;
        a.src[6] = sw2; a.dst[6] = sw2h_p;
        int acc = 0;
        int blks[7] = {BX, BW, BW, BW, BSW, BSW, BSW};
        for (int s = 0; s < 7; s++) { acc += blks[s]; a.blk_end[s] = acc; }
        f2h_all_kernel<<<acc, 256>>>(a);
    }

    // routed stage 1a: g1 = x@W1^T + b1 (gather tokens), N=512, K=1024
    gemm128<1,3><<<dim3(DFFE / 128, NTOK / 128, NEXP), 256, SMEM_TOTAL>>>(
        hx_p, w1h_p, b1, g1_p, nullptr, DMODEL, DFFE, DFFE);
    // routed stage 1b: h = silu(g1) * (x@W3^T + b3) -> fp16
    gemm128<1,4><<<dim3(DFFE / 128, NTOK / 128, NEXP), 256, SMEM_TOTAL>>>(
        hx_p, w3h_p, b3, h_p, g1_p, DMODEL, DFFE, DFFE);
    // routed stage 2: ypart[slot] = (h@W2^T + b2) * gate_w, N=1024, K=512
    gemm128<2,1><<<dim3(DMODEL / 128, NTOK / 128, NEXP), 256, SMEM_TOTAL>>>(
        h_p, w2h_p, b2, yp_p, nullptr, DFFE, DMODEL, DMODEL);

    // shared stage 1a/1b: dense, N=1024, K=1024
    gemm128<0,3><<<dim3(DFFS / 128, NTOK / 128, 1), 256, SMEM_TOTAL>>>(
        hx_p, sw1h_p, sb1, g1_p, nullptr, DMODEL, DFFS, DFFS);
    gemm128<0,4><<<dim3(DFFS / 128, NTOK / 128, 1), 256, SMEM_TOTAL>>>(
        hx_p, sw3h_p, sb3, hs_p, g1_p, DMODEL, DFFS, DFFS);

    // shared stage 2 + combine: out = hs@sW2^T + sb2 + ypart[2m] + ypart[2m+1]
    gemm128<0,2><<<dim3(DMODEL / 128, NTOK / 128, 1), 256, SMEM_TOTAL>>>(
        hs_p, sw2h_p, sb2, out, nullptr, DMODEL, DMODEL, DMODEL);
}

// round 11
// speedup vs baseline: 2.4009x; 1.1389x over previous
#include <cuda_runtime.h>
#include <cuda_fp16.h>
#include <cstdint>
#include <math.h>

#define NTOK   8192
#define DMODEL 1024
#define DFFE   512
#define NEXP   16
#define DFFS   1024

// ---------------- scratch (device globals; no allocations) ----------------
__device__ int   d_cnt[NEXP];
__device__ int   d_lists[NEXP * NTOK];
__device__ float d_gw[2 * NTOK];
__device__ float d_ypart[(size_t)2 * NTOK * DMODEL];   // routed partials (fp32)
// fp16 operands
__device__ __half d_hx [(size_t)NTOK * DMODEL];
__device__ __half d_w1h[(size_t)NEXP * DFFE * DMODEL];
__device__ __half d_w3h[(size_t)NEXP * DFFE * DMODEL];
__device__ __half d_w2h[(size_t)NEXP * DMODEL * DFFE];
__device__ __half d_sw1h[(size_t)DFFS * DMODEL];
__device__ __half d_sw3h[(size_t)DFFS * DMODEL];
__device__ __half d_sw2h[(size_t)DMODEL * DFFS];
__device__ __half d_h [(size_t)2 * NTOK * DFFE];       // routed hidden (fp16)
__device__ __half d_hs[(size_t)NTOK * DFFS];           // shared hidden (fp16)

__device__ __forceinline__ float fsigmoid(float v) { return 1.f / (1.f + __expf(-v)); }
__device__ __forceinline__ uint32_t smem_u32(const void* p) {
    uint32_t a;
    asm("{ .reg .u64 t; cvta.to.shared.u64 t, %1; cvt.u32.u64 %0, t; }" : "=r"(a) : "l"(p));
    return a;
}
__device__ __forceinline__ void mma_f16(float* c, const uint32_t* a, uint32_t b0, uint32_t b1) {
    asm volatile("mma.sync.aligned.m16n8k16.row.col.f32.f16.f16.f32 "
        "{%0,%1,%2,%3}, {%4,%5,%6,%7}, {%8,%9}, {%0,%1,%2,%3};"
        : "+f"(c[0]), "+f"(c[1]), "+f"(c[2]), "+f"(c[3])
        : "r"(a[0]), "r"(a[1]), "r"(a[2]), "r"(a[3]), "r"(b0), "r"(b1));
}
__device__ __forceinline__ void ldsm4(uint32_t* r, uint32_t addr) {
    asm volatile("ldmatrix.sync.aligned.m8n8.x4.shared.b16 {%0,%1,%2,%3}, [%4];"
        : "=r"(r[0]), "=r"(r[1]), "=r"(r[2]), "=r"(r[3]) : "r"(addr));
}
__device__ __forceinline__ void cp_async16(uint32_t dst, const void* src) {
    asm volatile("cp.async.cg.shared.global [%0], [%1], 16;" :: "r"(dst), "l"(src));
}
__device__ __forceinline__ uint4 pack_h8(float4 u, float4 v) {
    uint4 o;
    half2 h0 = __floats2half2_rn(u.x, u.y);
    half2 h1 = __floats2half2_rn(u.z, u.w);
    half2 h2 = __floats2half2_rn(v.x, v.y);
    half2 h3 = __floats2half2_rn(v.z, v.w);
    o.x = *(uint32_t*)&h0; o.y = *(uint32_t*)&h1;
    o.z = *(uint32_t*)&h2; o.w = *(uint32_t*)&h3;
    return o;
}

// ---------------- smem layout ----------------
// BK=64 halfs (128B data/row), row stride 144B. LDSM conflict-free (8x36w mod 32).
#define BK       64
#define RS       144
#define NSTAGE   3
#define BUFBYTES (128 * RS)                    // 18432
#define ABUF_OFF 0
#define BBUF_OFF (NSTAGE * BUFBYTES)           // 55296
#define SLOT_OFF (2 * NSTAGE * BUFBYTES)       // 110592
#define BIAS_OFF (SLOT_OFF + 512)
#define SMEM_TOTAL (BIAS_OFF + 512)            // 111616

// ---------------- small kernels ----------------
__global__ void zero_cnt_kernel() {
    if (threadIdx.x < NEXP) d_cnt[threadIdx.x] = 0;
}

// merged fp32->fp16 conversion over 7 segments
struct F2HArgs {
    const float* src[7];
    __half*      dst[7];
    int          blk_end[7];   // cumulative block counts (2048 elems per block)
};
__global__ void f2h_all_kernel(F2HArgs args) {
    int b = blockIdx.x;
    int seg = 0;
#pragma unroll
    for (int s = 0; s < 7; s++) if (b >= args.blk_end[s]) seg = s + 1;
    int b0 = (seg == 0) ? 0 : args.blk_end[seg - 1];
    size_t i = ((size_t)(b - b0) * blockDim.x + threadIdx.x) * 8;
    const float* src = args.src[seg];
    __half* dst = args.dst[seg];
    float4 a = *(const float4*)(src + i);
    float4 v = *(const float4*)(src + i + 4);
    *(uint4*)(dst + i) = pack_h8(a, v);
}

__global__ void gate_kernel(const float* __restrict__ x,
                            const float* __restrict__ gw,
                            const float* __restrict__ ebias)
{
    int warp = (blockIdx.x * blockDim.x + threadIdx.x) >> 5;
    int lane = threadIdx.x & 31;
    if (warp >= NTOK) return;
    const float* xr = x + (size_t)warp * DMODEL;
    float xv[32];
#pragma unroll
    for (int j = 0; j < 32; j++) xv[j] = xr[lane + 32 * j];
    float logits[NEXP];
#pragma unroll
    for (int e = 0; e < NEXP; e++) {
        const float* wr = gw + e * DMODEL;
        float acc = 0.f;
#pragma unroll
        for (int j = 0; j < 32; j++) acc += xv[j] * wr[lane + 32 * j];
#pragma unroll
        for (int o = 16; o > 0; o >>= 1) acc += __shfl_xor_sync(0xffffffffu, acc, o);
        logits[e] = acc;
    }
    if (lane == 0) {
        int i0 = -1, i1 = -1;
        float v0 = -INFINITY, v1 = -INFINITY;
#pragma unroll
        for (int e = 0; e < NEXP; e++) {
            float b = logits[e] + ebias[e];
            if (b > v0) { v1 = v0; i1 = i0; v0 = b; i0 = e; }
            else if (b > v1) { v1 = b; i1 = e; }
        }
        float s0 = fsigmoid(logits[i0]);
        float s1 = fsigmoid(logits[i1]);
        float inv = 1.f / (s0 + s1 + 1e-10f);
        int p0 = atomicAdd(&d_cnt[i0], 1);
        d_lists[i0 * NTOK + p0] = warp * 2 + 0;
        d_gw[warp * 2 + 0] = s0 * inv;
        int p1 = atomicAdd(&d_cnt[i1], 1);
        d_lists[i1 * NTOK + p1] = warp * 2 + 1;
        d_gw[warp * 2 + 1] = s1 * inv;
    }
}

// ============ fused stage-1: dual-B (W1+W3 interleaved) + SwiGLU ============
// CTA: 128 m-rows x 64 h-columns. B tile 128 rows:
//   row r: wn_r = r>>6, half = (r>>5)&1, sub = r&31
//   half 0 -> W1 row (n0 + wn_r*32 + sub), half 1 -> W3 same n.
// Warp wn: frags f=0..3 -> W1 (n = n0 + wn*32 + 8f), f=4..7 -> W3 same n.
// h = silu(g1 + b1) * (g3 + b3) -> fp16 Out.
template<int GATHER>
__global__ void __launch_bounds__(256, 2)
gemm_dual(const __half* __restrict__ A,
          const __half* __restrict__ W1b, const __half* __restrict__ W3b,
          const float* __restrict__ b1b, const float* __restrict__ b3b,
          __half* __restrict__ Out, int K, int NW, int ldo)
{
    int e  = blockIdx.z;
    int m0 = blockIdx.y * 128;
    int n0 = blockIdx.x * 64;
    int Mv = NTOK;
    const int* list = d_lists + e * NTOK;
    if (GATHER != 0) { Mv = d_cnt[e]; if (m0 >= Mv) return; }
    const __half* W1 = W1b + (size_t)e * NW * K;
    const __half* W3 = W3b + (size_t)e * NW * K;

    extern __shared__ char smem[];
    uint32_t sbase = smem_u32(smem);
    int*   sslot = (int*)(smem + SLOT_OFF);
    float* sB1   = (float*)(smem + BIAS_OFF);
    float* sB3   = sB1 + 64;

    int tid = threadIdx.x;
    if (tid < 128) {
        int m = m0 + tid;
        sslot[tid] = (GATHER != 0) ? list[m < Mv ? m : Mv - 1] : m;
    } else {
        int j = tid - 128;
        if (j < 64) sB1[j] = b1b[(size_t)e * NW + n0 + j];
        else        sB3[j - 64] = b3b[(size_t)e * NW + n0 + j - 64];
    }
    __syncthreads();

    // cp.async writer: 4 x 16B per matrix per tile per thread
    const __half* aSrc[4]; const __half* bSrc[4]; uint32_t dstOff[4];
#pragma unroll
    for (int i = 0; i < 4; i++) {
        int idx = tid + i * 256;            // 0..1023
        int row = idx >> 3, c = idx & 7;
        int slot = sslot[row];
        int ar = (GATHER == 1) ? (slot >> 1) : slot;
        aSrc[i] = A + (size_t)ar * K + c * 8;
        int wn_r = row >> 6, half = (row >> 5) & 1, sub = row & 31;
        const __half* Wsel = half ? W3 : W1;
        bSrc[i] = Wsel + (size_t)(n0 + wn_r * 32 + sub) * K + c * 8;
        dstOff[i] = (uint32_t)(row * RS + c * 16);
    }

    int wid = tid >> 5, lane = tid & 31;
    int wm = wid & 3, wn = wid >> 2;
    int lr = lane >> 2, lc = lane & 3;
    int mat = lane >> 3, rr = lane & 7;

    uint32_t aOff[2], bOff[4];
#pragma unroll
    for (int mf = 0; mf < 2; mf++)
        aOff[mf] = (uint32_t)((wm * 32 + mf * 16 + (mat & 1) * 8 + rr) * RS + (mat >> 1) * 16);
#pragma unroll
    for (int fp = 0; fp < 4; fp++)
        bOff[fp] = (uint32_t)((wn * 64 + fp * 16 + (mat >> 1) * 8 + rr) * RS + (mat & 1) * 16);

    float acc[2][8][4] = {};
    int T = K / BK;

    auto issue_tile = [&](int t) {
        int buf = t % NSTAGE;
        uint32_t aB = sbase + ABUF_OFF + buf * BUFBYTES;
        uint32_t bB = sbase + BBUF_OFF + buf * BUFBYTES;
        int k0 = t * BK;
#pragma unroll
        for (int i = 0; i < 4; i++) {
            cp_async16(aB + dstOff[i], aSrc[i] + k0);
            cp_async16(bB + dstOff[i], bSrc[i] + k0);
        }
        asm volatile("cp.async.commit_group;" ::: "memory");
    };

    issue_tile(0);
    issue_tile(1);

    for (int t = 0; t < T; t++) {
        asm volatile("cp.async.wait_group 1;" ::: "memory");
        __syncthreads();
        uint32_t abuf = sbase + ABUF_OFF + (t % NSTAGE) * BUFBYTES;
        uint32_t bbuf = sbase + BBUF_OFF + (t % NSTAGE) * BUFBYTES;
#pragma unroll
        for (int kk = 0; kk < 4; kk++) {
            uint32_t koff = kk * 32;
            uint32_t a[2][4];
            ldsm4(a[0], abuf + aOff[0] + koff);
            ldsm4(a[1], abuf + aOff[1] + koff);
#pragma unroll
            for (int fp = 0; fp < 4; fp++) {
                uint32_t b[4];
                ldsm4(b, bbuf + bOff[fp] + koff);
                mma_f16(acc[0][2 * fp],     a[0], b[0], b[1]);
                mma_f16(acc[1][2 * fp],     a[1], b[0], b[1]);
                mma_f16(acc[0][2 * fp + 1], a[0], b[2], b[3]);
                mma_f16(acc[1][2 * fp + 1], a[1], b[2], b[3]);
            }
        }
        if (t + 2 < T) {
            issue_tile(t + 2);
        } else {
            asm volatile("cp.async.commit_group;" ::: "memory");
        }
    }

    // fused SwiGLU epilogue: f<4 = g (W1 block), f+4 = u (W3 block), same n
#pragma unroll
    for (int mf = 0; mf < 2; mf++) {
#pragma unroll
        for (int half = 0; half < 2; half++) {
            int rt = wm * 32 + mf * 16 + half * 8 + lr;
            int m = m0 + rt;
            if (GATHER != 0 && m >= Mv) continue;
            int orow = sslot[rt];
#pragma unroll
            for (int f = 0; f < 4; f++) {
                int nl = wn * 32 + 8 * f + 2 * lc;
                float g0 = acc[mf][f][half * 2 + 0] + sB1[nl];
                float g1 = acc[mf][f][half * 2 + 1] + sB1[nl + 1];
                float u0 = acc[mf][f + 4][half * 2 + 0] + sB3[nl];
                float u1 = acc[mf][f + 4][half * 2 + 1] + sB3[nl + 1];
                float h0 = g0 * fsigmoid(g0) * u0;
                float h1 = g1 * fsigmoid(g1) * u1;
                *(half2*)(Out + (size_t)orow * ldo + n0 + nl) = __floats2half2_rn(h0, h1);
            }
        }
    }
}

// ---------------- stage-2 128x128x64 fp16 GEMM, cp.async 3-stage ----------------
// GATHER: 0 dense, 2 gather slot
// EPI: 1 (acc+b)*gw -> ypart(f32); 2 acc+b+ypart2 -> out(f32)
template<int GATHER, int EPI>
__global__ void __launch_bounds__(256, 2)
gemm128(const __half* __restrict__ A, const __half* __restrict__ Wb,
        const float* __restrict__ bb, void* __restrict__ OutV,
        int K, int NW, int ldo)
{
    int e  = blockIdx.z;
    int m0 = blockIdx.y * 128;
    int n0 = blockIdx.x * 128;
    int Mv = NTOK;
    const int* list = d_lists + e * NTOK;
    if (GATHER != 0) { Mv = d_cnt[e]; if (m0 >= Mv) return; }
    const __half* W = Wb + (size_t)e * NW * K;

    extern __shared__ char smem[];
    uint32_t sbase = smem_u32(smem);
    int*   sslot = (int*)(smem + SLOT_OFF);
    float* sBB   = (float*)(smem + BIAS_OFF);

    int tid = threadIdx.x;
    if (tid < 128) {
        int m = m0 + tid;
        sslot[tid] = (GATHER != 0) ? list[m < Mv ? m : Mv - 1] : m;
    } else {
        sBB[tid - 128] = bb[(size_t)e * NW + n0 + (tid - 128)];
    }
    __syncthreads();

    const __half* aSrc[4]; const __half* bSrc[4]; uint32_t dstOff[4];
#pragma unroll
    for (int i = 0; i < 4; i++) {
        int idx = tid + i * 256;
        int row = idx >> 3, c = idx & 7;
        int slot = sslot[row];
        aSrc[i] = A + (size_t)slot * K + c * 8;
        bSrc[i] = W + (size_t)(n0 + row) * K + c * 8;
        dstOff[i] = (uint32_t)(row * RS + c * 16);
    }

    int wid = tid >> 5, lane = tid & 31;
    int wm = wid & 3, wn = wid >> 2;
    int lr = lane >> 2, lc = lane & 3;
    int mat = lane >> 3, rr = lane & 7;

    uint32_t aOff[2], bOff[4];
#pragma unroll
    for (int mf = 0; mf < 2; mf++)
        aOff[mf] = (uint32_t)((wm * 32 + mf * 16 + (mat & 1) * 8 + rr) * RS + (mat >> 1) * 16);
#pragma unroll
    for (int fp = 0; fp < 4; fp++)
        bOff[fp] = (uint32_t)((wn * 64 + fp * 16 + (mat >> 1) * 8 + rr) * RS + (mat & 1) * 16);

    float acc[2][8][4] = {};
    int T = K / BK;

    auto issue_tile = [&](int t) {
        int buf = t % NSTAGE;
        uint32_t aB = sbase + ABUF_OFF + buf * BUFBYTES;
        uint32_t bB = sbase + BBUF_OFF + buf * BUFBYTES;
        int k0 = t * BK;
#pragma unroll
        for (int i = 0; i < 4; i++) {
            cp_async16(aB + dstOff[i], aSrc[i] + k0);
            cp_async16(bB + dstOff[i], bSrc[i] + k0);
        }
        asm volatile("cp.async.commit_group;" ::: "memory");
    };

    issue_tile(0);
    issue_tile(1);

    for (int t = 0; t < T; t++) {
        asm volatile("cp.async.wait_group 1;" ::: "memory");
        __syncthreads();
        uint32_t abuf = sbase + ABUF_OFF + (t % NSTAGE) * BUFBYTES;
        uint32_t bbuf = sbase + BBUF_OFF + (t % NSTAGE) * BUFBYTES;
#pragma unroll
        for (int kk = 0; kk < 4; kk++) {
            uint32_t koff = kk * 32;
            uint32_t a[2][4];
            ldsm4(a[0], abuf + aOff[0] + koff);
            ldsm4(a[1], abuf + aOff[1] + koff);
#pragma unroll
            for (int fp = 0; fp < 4; fp++) {
                uint32_t b[4];
                ldsm4(b, bbuf + bOff[fp] + koff);
                mma_f16(acc[0][2 * fp],     a[0], b[0], b[1]);
                mma_f16(acc[1][2 * fp],     a[1], b[0], b[1]);
                mma_f16(acc[0][2 * fp + 1], a[0], b[2], b[3]);
                mma_f16(acc[1][2 * fp + 1], a[1], b[2], b[3]);
            }
        }
        if (t + 2 < T) {
            issue_tile(t + 2);
        } else {
            asm volatile("cp.async.commit_group;" ::: "memory");
        }
    }

#pragma unroll
    for (int mf = 0; mf < 2; mf++) {
#pragma unroll
        for (int half = 0; half < 2; half++) {
            int rt = wm * 32 + mf * 16 + half * 8 + lr;
            int m = m0 + rt;
            if (GATHER != 0 && m >= Mv) continue;
            int orow = sslot[rt];
            float sc = (EPI == 1) ? d_gw[orow] : 0.f;
#pragma unroll
            for (int f = 0; f < 8; f++) {
                int nb = wn * 64 + 8 * f + 2 * lc;
                float c0 = acc[mf][f][half * 2 + 0] + sBB[nb];
                float c1 = acc[mf][f][half * 2 + 1] + sBB[nb + 1];
                if (EPI == 1) {
                    float* O = (float*)OutV;
                    *(float2*)(O + (size_t)orow * ldo + n0 + nb) =
                        make_float2(c0 * sc, c1 * sc);
                } else {
                    const float* y0 = d_ypart + (size_t)(2 * m) * DMODEL + n0 + nb;
                    const float* y1 = y0 + DMODEL;
                    float2 a2 = *(const float2*)y0;
                    float2 b2 = *(const float2*)y1;
                    float* O = (float*)OutV;
                    *(float2*)(O + (size_t)m * ldo + n0 + nb) =
                        make_float2(c0 + a2.x + b2.x, c1 + a2.y + b2.y);
                }
            }
        }
    }
}

// ---------------- launch ----------------
extern "C" void kernel_launch(void* const* d_in, const int* in_sizes, int n_in,
                              void* d_out, int out_size)
{
    const float* x   = (const float*)d_in[0];
    const float* gw  = (const float*)d_in[1];
    const float* eb  = (const float*)d_in[2];
    const float* w1  = (const float*)d_in[3];
    const float* b1  = (const float*)d_in[4];
    const float* w3  = (const float*)d_in[5];
    const float* b3  = (const float*)d_in[6];
    const float* w2  = (const float*)d_in[7];
    const float* b2  = (const float*)d_in[8];
    const float* sw1 = (const float*)d_in[9];
    const float* sb1 = (const float*)d_in[10];
    const float* sw3 = (const float*)d_in[11];
    const float* sb3 = (const float*)d_in[12];
    const float* sw2 = (const float*)d_in[13];
    const float* sb2 = (const float*)d_in[14];
    float* out = (float*)d_out;

    float*  yp_p;  cudaGetSymbolAddress((void**)&yp_p,  d_ypart);
    __half* hx_p;  cudaGetSymbolAddress((void**)&hx_p,  d_hx);
    __half* w1h_p; cudaGetSymbolAddress((void**)&w1h_p, d_w1h);
    __half* w3h_p; cudaGetSymbolAddress((void**)&w3h_p, d_w3h);
    __half* w2h_p; cudaGetSymbolAddress((void**)&w2h_p, d_w2h);
    __half* sw1h_p; cudaGetSymbolAddress((void**)&sw1h_p, d_sw1h);
    __half* sw3h_p; cudaGetSymbolAddress((void**)&sw3h_p, d_sw3h);
    __half* sw2h_p; cudaGetSymbolAddress((void**)&sw2h_p, d_sw2h);
    __half* h_p;   cudaGetSymbolAddress((void**)&h_p,   d_h);
    __half* hs_p;  cudaGetSymbolAddress((void**)&hs_p,  d_hs);

    cudaFuncSetAttribute(gemm_dual<1>, cudaFuncAttributeMaxDynamicSharedMemorySize, SMEM_TOTAL);
    cudaFuncSetAttribute(gemm_dual<0>, cudaFuncAttributeMaxDynamicSharedMemorySize, SMEM_TOTAL);
    cudaFuncSetAttribute(gemm128<2,1>, cudaFuncAttributeMaxDynamicSharedMemorySize, SMEM_TOTAL);
    cudaFuncSetAttribute(gemm128<0,2>, cudaFuncAttributeMaxDynamicSharedMemorySize, SMEM_TOTAL);

    zero_cnt_kernel<<<1, 32>>>();
    gate_kernel<<<(NTOK * 32) / 256, 256>>>(x, gw, eb);

    // merged fp32 -> fp16 conversions (2048 elems per block)
    {
        const int BX  = (int)(((size_t)NTOK * DMODEL) / 2048);        // 4096
        const int BW  = (int)(((size_t)NEXP * DFFE * DMODEL) / 2048); // 4096
        const int BSW = (int)(((size_t)DFFS * DMODEL) / 2048);        // 512
        F2HArgs a;
        a.src[0] = x;   a.dst[0] = hx_p;
        a.src[1] = w1;  a.dst[1] = w1h_p;
        a.src[2] = w3;  a.dst[2] = w3h_p;
        a.src[3] = w2;  a.dst[3] = w2h_p;
        a.src[4] = sw1; a.dst[4] = sw1h_p;
        a.src[5] = sw3; a.dst[5] = sw3h_p;
        a.src[6] = sw2; a.dst[6] = sw2h_p;
        int acc = 0;
        int blks[7] = {BX, BW, BW, BW, BSW, BSW, BSW};
        for (int s = 0; s < 7; s++) { acc += blks[s]; a.blk_end[s] = acc; }
        f2h_all_kernel<<<acc, 256>>>(a);
    }

    // routed stage 1 (fused dual): h = silu(x@W1^T+b1) * (x@W3^T+b3), fp16
    gemm_dual<1><<<dim3(DFFE / 64, NTOK / 128, NEXP), 256, SMEM_TOTAL>>>(
        hx_p, w1h_p, w3h_p, b1, b3, h_p, DMODEL, DFFE, DFFE);

    // routed stage 2: ypart[slot] = (h@W2^T + b2) * gate_w, N=1024, K=512
    gemm128<2,1><<<dim3(DMODEL / 128, NTOK / 128, NEXP), 256, SMEM_TOTAL>>>(
        h_p, w2h_p, b2, yp_p, DFFE, DMODEL, DMODEL);

    // shared stage 1 (fused dual): dense
    gemm_dual<0><<<dim3(DFFS / 64, NTOK / 128, 1), 256, SMEM_TOTAL>>>(
        hx_p, sw1h_p, sw3h_p, sb1, sb3, hs_p, DMODEL, DFFS, DFFS);

    // shared stage 2 + combine: out = hs@sW2^T + sb2 + ypart[2m] + ypart[2m+1]
    gemm128<0,2><<<dim3(DMODEL / 128, NTOK / 128, 1), 256, SMEM_TOTAL>>>(
        hs_p, sw2h_p, sb2, out, DMODEL, DMODEL, DMODEL);
}